// round 10
// baseline (speedup 1.0000x reference)
#include <cuda_runtime.h>
#include <cuda_fp16.h>
#include <cstdint>

#define N 8192

// -------------------- device scratch ---------------------------------------
__device__ float g_xqm[N * 64];
__device__ float g_xqv[N * 96];
__device__ float g_qnm[N], g_qnv[N], g_Xnm[N], g_Xnv[N];
__device__ float g_LpA0[N * 32], g_LpB0[N * 32];   // Lambda partials (k-halves)
__device__ float g_LpA1[N * 32], g_LpB1[N * 32];
__device__ float g_zm[N * 32], g_zv[N * 32];
__device__ __align__(16) __half g_Xmh[N * 64];          // X hi (phase1 hi-only)
__device__ __align__(16) __half g_Xvh[N * 96];
__device__ __align__(16) __half g_Lth0[32 * N], g_Ltl0[32 * N];
__device__ __align__(16) __half g_Lth1[32 * N], g_Ltl1[32 * N];
__device__ __align__(16) __half g_Zth0[32 * N], g_Ztl0[32 * N];
__device__ __align__(16) __half g_Zth1[32 * N], g_Ztl1[32 * N];

// -------------------- mma helpers (sm_80+ HMMA fp16) ------------------------
__device__ __forceinline__ void mma_f16(float c[4], const uint32_t a[4],
                                        uint32_t b0, uint32_t b1) {
    asm volatile(
        "mma.sync.aligned.m16n8k16.row.col.f32.f16.f16.f32 "
        "{%0,%1,%2,%3}, {%4,%5,%6,%7}, {%8,%9}, {%0,%1,%2,%3};"
        : "+f"(c[0]), "+f"(c[1]), "+f"(c[2]), "+f"(c[3])
        : "r"(a[0]), "r"(a[1]), "r"(a[2]), "r"(a[3]), "r"(b0), "r"(b1));
}
__device__ __forceinline__ uint32_t packhf(float lo, float hi) {
    uint32_t r;
    asm("cvt.rn.f16x2.f32 %0, %1, %2;" : "=r"(r) : "f"(hi), "f"(lo));
    return r;
}
__device__ __forceinline__ float2 up2(uint32_t w) {
    __half2 h = *reinterpret_cast<__half2*>(&w);
    return __half22float2(h);
}
__device__ __forceinline__ uint32_t ldsw(const __half* p) {
    return *(const uint32_t*)p;
}
// group-scoped named barrier: 256 threads of group g
#define GBAR(g) asm volatile("bar.sync %0, 256;" :: "r"(1 + (g)) : "memory")

// -------------------- prep kernels ------------------------------------------
__global__ void prep_q_kernel(const float* __restrict__ x_mu,
                              const float* __restrict__ y_eta,
                              const float* __restrict__ y_mean,
                              const float* __restrict__ y_var) {
    int q = (blockIdx.x * blockDim.x + threadIdx.x) >> 5;
    int lane = threadIdx.x & 31;
    if (q >= N) return;
    float a = x_mu[q * 32 + lane];
    float m = y_mean[q * 32 + lane] + y_var[q * 32 + lane];
    float e = 0.01f * y_eta[(N - 1 - q) * 32 + lane];
    g_xqm[q * 64 + lane] = a;       g_xqm[q * 64 + 32 + lane] = m;
    g_xqv[q * 96 + lane] = a;       g_xqv[q * 96 + 32 + lane] = e;
    g_xqv[q * 96 + 64 + lane] = m;
    float nm = a * a + m * m, nv = nm + e * e;
    #pragma unroll
    for (int o = 16; o; o >>= 1) {
        nm += __shfl_xor_sync(0xffffffffu, nm, o);
        nv += __shfl_xor_sync(0xffffffffu, nv, o);
    }
    if (lane == 0) { g_qnm[q] = nm; g_qnv[q] = nv; }
}

__global__ void prep_X_kernel(const float* __restrict__ Xm,
                              const float* __restrict__ Xv) {
    int i = (blockIdx.x * blockDim.x + threadIdx.x) >> 5;
    int lane = threadIdx.x & 31;
    if (i >= N) return;
    float nm = 0.f, nv = 0.f;
    #pragma unroll
    for (int c = 0; c < 64; c += 32) {
        float v = Xm[(size_t)i * 64 + c + lane];
        nm += v * v;
        g_Xmh[(size_t)i * 64 + c + lane] = __float2half_rn(v);
    }
    #pragma unroll
    for (int c = 0; c < 96; c += 32) {
        float v = Xv[(size_t)i * 96 + c + lane];
        nv += v * v;
        g_Xvh[(size_t)i * 96 + c + lane] = __float2half_rn(v);
    }
    #pragma unroll
    for (int o = 16; o; o >>= 1) {
        nm += __shfl_xor_sync(0xffffffffu, nm, o);
        nv += __shfl_xor_sync(0xffffffffu, nv, o);
    }
    if (lane == 0) { g_Xnm[i] = nm; g_Xnv[i] = nv; }
}

// Z -> transposed fp16 hi/lo [32][N]
__global__ void zsplit_kernel(const float* __restrict__ Z0,
                              const float* __restrict__ Z1) {
    int idx = blockIdx.x * blockDim.x + threadIdx.x;
    if (idx >= 2 * 32 * N) return;
    int t = idx >= 32 * N;
    int j = idx - t * 32 * N;
    int n = j / N, k = j - n * N;
    float v = (t ? Z1 : Z0)[(size_t)k * 32 + n];
    __half h = __float2half_rn(v);
    (t ? g_Zth1 : g_Zth0)[j] = h;
    (t ? g_Ztl1 : g_Ztl0)[j] = __float2half_rn(v - __half2float(h));
}

// -------------------- Lambda = kXX_inv @ Z on HMMA (double-buffered) --------
#define LSM_A (128 * 36)
#define LSM_Z (32 * 36)
#define LAMBDA_SMEM ((4 * LSM_A + 4 * LSM_Z) * 4)   // 92160 B

__global__ __launch_bounds__(256, 2) void lambda_hmma_kernel(
    const float* __restrict__ A0, const float* __restrict__ A1) {
    extern __shared__ uint32_t lsm[];
    uint32_t* sAh = lsm;                              // [2][128*36]
    uint32_t* sAl = lsm + 2 * LSM_A;
    uint32_t* sZh = lsm + 4 * LSM_A;                  // [2][32*36]
    uint32_t* sZl = lsm + 4 * LSM_A + 2 * LSM_Z;

    const int task = blockIdx.y, kh = blockIdx.z;
    const float* A = task ? A1 : A0;
    const __half* Zh = task ? g_Zth1 : g_Zth0;
    const __half* Zl = task ? g_Ztl1 : g_Ztl0;
    float* Lp = task ? (kh ? g_LpB1 : g_LpA1) : (kh ? g_LpB0 : g_LpA0);

    const int tid = threadIdx.x, lane = tid & 31, w = tid >> 5;
    const int t = lane & 3, qr = lane >> 2;
    const int rb = blockIdx.x * 128;
    const int kb0 = kh * (N / 2);
    const int zn = tid >> 3, zw4 = (tid & 7) * 4;

    float4 pa[8];
    uint4 pzh, pzl;

    // load + stage chunk 0 into buffer 0
    #pragma unroll
    for (int it = 0; it < 8; it++) {
        int idx = tid + it * 256;
        int r = idx >> 4, c4 = idx & 15;
        pa[it] = *(const float4*)&A[(size_t)(rb + r) * N + kb0 + c4 * 4];
    }
    pzh = ((const uint4*)Zh)[(zn * (N / 2) + kb0 / 2 + zw4) >> 2];
    pzl = ((const uint4*)Zl)[(zn * (N / 2) + kb0 / 2 + zw4) >> 2];
    #pragma unroll
    for (int it = 0; it < 8; it++) {
        int idx = tid + it * 256;
        int r = idx >> 4, c4 = idx & 15;
        float4 v = pa[it];
        uint32_t h0 = packhf(v.x, v.y);
        uint32_t h1 = packhf(v.z, v.w);
        float2 f0 = up2(h0), f1 = up2(h1);
        *(uint2*)&sAh[r * 36 + c4 * 2] = make_uint2(h0, h1);
        *(uint2*)&sAl[r * 36 + c4 * 2] =
            make_uint2(packhf(v.x - f0.x, v.y - f0.y),
                       packhf(v.z - f1.x, v.w - f1.y));
    }
    *(uint4*)&sZh[zn * 36 + zw4] = pzh;
    *(uint4*)&sZl[zn * 36 + zw4] = pzl;

    // prefetch chunk 1
    {
        const int ko = kb0 + 64;
        #pragma unroll
        for (int it = 0; it < 8; it++) {
            int idx = tid + it * 256;
            int r = idx >> 4, c4 = idx & 15;
            pa[it] = *(const float4*)&A[(size_t)(rb + r) * N + ko + c4 * 4];
        }
        pzh = ((const uint4*)Zh)[(zn * (N / 2) + ko / 2 + zw4) >> 2];
        pzl = ((const uint4*)Zl)[(zn * (N / 2) + ko / 2 + zw4) >> 2];
    }

    float zc[4][4];
    #pragma unroll
    for (int i = 0; i < 4; i++)
        #pragma unroll
        for (int j = 0; j < 4; j++) zc[i][j] = 0.f;

    for (int cb = 0; cb < 64; cb++) {
        __syncthreads();   // buf[cb&1] staged & buf[(cb+1)&1] free (prev reads done)
        const uint32_t* bAh = sAh + (cb & 1) * LSM_A;
        const uint32_t* bAl = sAl + (cb & 1) * LSM_A;
        const uint32_t* bZh = sZh + (cb & 1) * LSM_Z;
        const uint32_t* bZl = sZl + (cb & 1) * LSM_Z;

        #pragma unroll
        for (int kt = 0; kt < 4; kt++) {
            const int kw = kt * 8 + t;
            uint32_t ah[4], al[4];
            ah[0] = bAh[(w * 16 + qr) * 36 + kw];
            ah[1] = bAh[(w * 16 + qr + 8) * 36 + kw];
            ah[2] = bAh[(w * 16 + qr) * 36 + kw + 4];
            ah[3] = bAh[(w * 16 + qr + 8) * 36 + kw + 4];
            al[0] = bAl[(w * 16 + qr) * 36 + kw];
            al[1] = bAl[(w * 16 + qr + 8) * 36 + kw];
            al[2] = bAl[(w * 16 + qr) * 36 + kw + 4];
            al[3] = bAl[(w * 16 + qr + 8) * 36 + kw + 4];
            #pragma unroll
            for (int nt = 0; nt < 4; nt++) {
                const int nc = nt * 8 + qr;
                uint32_t bh0 = bZh[nc * 36 + kw], bh1 = bZh[nc * 36 + kw + 4];
                uint32_t bl0 = bZl[nc * 36 + kw], bl1 = bZl[nc * 36 + kw + 4];
                mma_f16(zc[nt], ah, bh0, bh1);
                mma_f16(zc[nt], ah, bl0, bl1);
                mma_f16(zc[nt], al, bh0, bh1);
            }
        }

        // stage chunk cb+1 into the other buffer (overlaps other warps' MMAs)
        if (cb < 63) {
            uint32_t* dAh = sAh + ((cb + 1) & 1) * LSM_A;
            uint32_t* dAl = sAl + ((cb + 1) & 1) * LSM_A;
            uint32_t* dZh = sZh + ((cb + 1) & 1) * LSM_Z;
            uint32_t* dZl = sZl + ((cb + 1) & 1) * LSM_Z;
            #pragma unroll
            for (int it = 0; it < 8; it++) {
                int idx = tid + it * 256;
                int r = idx >> 4, c4 = idx & 15;
                float4 v = pa[it];
                uint32_t h0 = packhf(v.x, v.y);
                uint32_t h1 = packhf(v.z, v.w);
                float2 f0 = up2(h0), f1 = up2(h1);
                *(uint2*)&dAh[r * 36 + c4 * 2] = make_uint2(h0, h1);
                *(uint2*)&dAl[r * 36 + c4 * 2] =
                    make_uint2(packhf(v.x - f0.x, v.y - f0.y),
                               packhf(v.z - f1.x, v.w - f1.y));
            }
            *(uint4*)&dZh[zn * 36 + zw4] = pzh;
            *(uint4*)&dZl[zn * 36 + zw4] = pzl;
        }
        if (cb < 62) {   // prefetch chunk cb+2
            const int ko = kb0 + (cb + 2) * 64;
            #pragma unroll
            for (int it = 0; it < 8; it++) {
                int idx = tid + it * 256;
                int r = idx >> 4, c4 = idx & 15;
                pa[it] = *(const float4*)&A[(size_t)(rb + r) * N + ko + c4 * 4];
            }
            pzh = ((const uint4*)Zh)[(zn * (N / 2) + ko / 2 + zw4) >> 2];
            pzl = ((const uint4*)Zl)[(zn * (N / 2) + ko / 2 + zw4) >> 2];
        }
    }

    const int row0 = rb + w * 16 + qr;
    #pragma unroll
    for (int nt = 0; nt < 4; nt++) {
        const int col = nt * 8 + 2 * t;
        Lp[(size_t)row0 * 32 + col]           = zc[nt][0];
        Lp[(size_t)row0 * 32 + col + 1]       = zc[nt][1];
        Lp[(size_t)(row0 + 8) * 32 + col]     = zc[nt][2];
        Lp[(size_t)(row0 + 8) * 32 + col + 1] = zc[nt][3];
    }
}

// Lambda partial sums -> transposed fp16 hi/lo [32][N]
__global__ void lsplit_kernel() {
    int idx = blockIdx.x * blockDim.x + threadIdx.x;
    if (idx >= 2 * 32 * N) return;
    int t = idx >= 32 * N;
    int j = idx - t * 32 * N;
    int n = j / N, k = j - n * N;
    size_t src = (size_t)k * 32 + n;
    float v = (t ? g_LpA1 : g_LpA0)[src] + (t ? g_LpB1 : g_LpB0)[src];
    __half h = __float2half_rn(v);
    (t ? g_Lth1 : g_Lth0)[j] = h;
    (t ? g_Ltl1 : g_Ltl0)[j] = __float2half_rn(v - __half2float(h));
}

// -------------------- fused HMMA kernel (group-scoped barriers) -------------
template <int D>
__device__ void ftc(char* smraw, const __half* Xh,
                    const float* Qg, const __half* Lth,
                    const __half* Ltl, const float* Xn,
                    const float* Qn, float* Zg, int qb) {
    constexpr int QS = D + 8;
    __half* sQh  = (__half*)smraw;
    __half* sXhB = sQh + 128 * QS;
    __half* sLhB = sXhB + 2 * 64 * QS;
    __half* sLlB = sLhB + 2 * 32 * 72;
    float* sXnB = (float*)(sLlB + 2 * 32 * 72);
    float* sRed = (float*)sXhB;            // reused after the chunk loop

    const int tid = threadIdx.x;
    const int g = tid >> 8, wtid = tid & 255;
    const int lane = tid & 31, w = wtid >> 5;
    const int t = lane & 3, qr = lane >> 2;
    const int wq0 = w * 16;
    __half* sXh = sXhB + g * 64 * QS;
    __half* sLh = sLhB + g * 32 * 72;
    __half* sLl = sLlB + g * 32 * 72;
    float* sXn = sXnB + g * 64;

    // Q -> SMEM fp16 hi (all 512 threads), then full-CTA sync
    for (int i = tid; i < 128 * D; i += 512) {
        int r = i / D, c = i - r * D;
        sQh[r * QS + c] = __float2half_rn(Qg[(size_t)(qb + r) * D + c]);
    }
    __syncthreads();
    const float qn0 = Qn[qb + wq0 + qr];
    const float qn1 = Qn[qb + wq0 + qr + 8];

    float zc[4][4];
    #pragma unroll
    for (int i = 0; i < 4; i++)
        #pragma unroll
        for (int j = 0; j < 4; j++) zc[i][j] = 0.f;

    for (int it = 0; it < 64; it++) {
        const int xb = (2 * it + g) * 64;
        // ---- stage this group's chunk ----
        #pragma unroll
        for (int i = wtid; i < 64 * (D / 4); i += 256) {
            int r = i / (D / 4), p = i - r * (D / 4);
            uint2 vh = ((const uint2*)Xh)[(size_t)(xb + r) * (D / 4) + p];
            *(uint2*)(sXh + r * QS + p * 4) = vh;
        }
        #pragma unroll
        for (int i = wtid; i < 32 * 16; i += 256) {
            int n = i >> 4, p = i & 15;
            uint2 vh = ((const uint2*)Lth)[(size_t)n * (N / 4) + xb / 4 + p];
            uint2 vl = ((const uint2*)Ltl)[(size_t)n * (N / 4) + xb / 4 + p];
            *(uint2*)(sLh + n * 72 + p * 4) = vh;
            *(uint2*)(sLl + n * 72 + p * 4) = vl;
        }
        if (wtid < 64) sXn[wtid] = Xn[xb + wtid];
        GBAR(g);

        // ---- phase 1: D1[16q x 64x] = Qh . Xh^T ----
        float c1[8][4];
        #pragma unroll
        for (int i = 0; i < 8; i++)
            #pragma unroll
            for (int j = 0; j < 4; j++) c1[i][j] = 0.f;

        #pragma unroll
        for (int kt = 0; kt < D / 16; kt++) {
            const int k0 = kt * 16 + 2 * t;
            uint32_t ah[4];
            ah[0] = ldsw(sQh + (wq0 + qr) * QS + k0);
            ah[1] = ldsw(sQh + (wq0 + qr + 8) * QS + k0);
            ah[2] = ldsw(sQh + (wq0 + qr) * QS + k0 + 8);
            ah[3] = ldsw(sQh + (wq0 + qr + 8) * QS + k0 + 8);
            #pragma unroll
            for (int nt = 0; nt < 8; nt++) {
                const int xr = nt * 8 + qr;
                uint32_t bh0 = ldsw(sXh + xr * QS + k0);
                uint32_t bh1 = ldsw(sXh + xr * QS + k0 + 8);
                mma_f16(c1[nt], ah, bh0, bh1);
            }
        }

        // ---- epilogue: exp -> P fragments (C m16n8 -> A m16k16 repack) ----
        uint32_t Ph[4][4], Pl[4][4];
        #pragma unroll
        for (int kt2 = 0; kt2 < 4; kt2++) {
            #pragma unroll
            for (int s = 0; s < 2; s++) {
                const int nt = 2 * kt2 + s;
                const int x0 = nt * 8 + 2 * t;
                float xna = sXn[x0], xnb = sXn[x0 + 1];
                float p0 = __expf(-0.0078125f * fmaxf(qn0 + xna - 2.f * c1[nt][0], 0.f));
                float p1 = __expf(-0.0078125f * fmaxf(qn0 + xnb - 2.f * c1[nt][1], 0.f));
                float p2 = __expf(-0.0078125f * fmaxf(qn1 + xna - 2.f * c1[nt][2], 0.f));
                float p3 = __expf(-0.0078125f * fmaxf(qn1 + xnb - 2.f * c1[nt][3], 0.f));
                uint32_t w0 = packhf(p0, p1);
                uint32_t w1 = packhf(p2, p3);
                float2 f0 = up2(w0), f1 = up2(w1);
                Ph[kt2][2 * s]     = w0;
                Ph[kt2][2 * s + 1] = w1;
                Pl[kt2][2 * s]     = packhf(p0 - f0.x, p1 - f0.y);
                Pl[kt2][2 * s + 1] = packhf(p2 - f1.x, p3 - f1.y);
            }
        }

        // ---- phase 2: z += P . Lambda^T (3 MMAs) ----
        #pragma unroll
        for (int kt2 = 0; kt2 < 4; kt2++) {
            const int k0 = kt2 * 16 + 2 * t;
            #pragma unroll
            for (int nt = 0; nt < 4; nt++) {
                const int nc = nt * 8 + qr;
                uint32_t bh0 = ldsw(sLh + nc * 72 + k0);
                uint32_t bh1 = ldsw(sLh + nc * 72 + k0 + 8);
                uint32_t bl0 = ldsw(sLl + nc * 72 + k0);
                uint32_t bl1 = ldsw(sLl + nc * 72 + k0 + 8);
                mma_f16(zc[nt], Ph[kt2], bh0, bh1);
                mma_f16(zc[nt], Ph[kt2], bl0, bl1);
                mma_f16(zc[nt], Pl[kt2], bh0, bh1);
            }
        }
        GBAR(g);
    }

    // ---- combine the two x-half partial sums (full-CTA sync) ----
    __syncthreads();
    const int row0 = wq0 + qr;
    if (g == 1) {
        #pragma unroll
        for (int nt = 0; nt < 4; nt++) {
            const int col = nt * 8 + 2 * t;
            sRed[row0 * 33 + col]           = zc[nt][0];
            sRed[row0 * 33 + col + 1]       = zc[nt][1];
            sRed[(row0 + 8) * 33 + col]     = zc[nt][2];
            sRed[(row0 + 8) * 33 + col + 1] = zc[nt][3];
        }
    }
    __syncthreads();
    if (g == 0) {
        #pragma unroll
        for (int nt = 0; nt < 4; nt++) {
            const int col = nt * 8 + 2 * t;
            float v0 = zc[nt][0] + sRed[row0 * 33 + col];
            float v1 = zc[nt][1] + sRed[row0 * 33 + col + 1];
            float v2 = zc[nt][2] + sRed[(row0 + 8) * 33 + col];
            float v3 = zc[nt][3] + sRed[(row0 + 8) * 33 + col + 1];
            Zg[(size_t)(qb + row0) * 32 + col]           = v0;
            Zg[(size_t)(qb + row0) * 32 + col + 1]       = v1;
            Zg[(size_t)(qb + row0 + 8) * 32 + col]       = v2;
            Zg[(size_t)(qb + row0 + 8) * 32 + col + 1]   = v3;
        }
    }
}

// D=96: (128*104 + 2*64*104 + 2*2*32*72) half + 2*64 f32 = 71680 + 512
#define FUSED_SMEM 72704

__global__ __launch_bounds__(512, 1) void fusedtc_kernel() {
    extern __shared__ char sm[];
    int task = blockIdx.x >> 6;
    int qb   = (blockIdx.x & 63) * 128;
    if (task == 0)
        ftc<64>(sm, g_Xmh, g_xqm, g_Lth0, g_Ltl0, g_Xnm, g_qnm, g_zm, qb);
    else
        ftc<96>(sm, g_Xvh, g_xqv, g_Lth1, g_Ltl1, g_Xnv, g_qnv, g_zv, qb);
}

// -------------------- combine ----------------------------------------------
__global__ void combine_kernel(const float* __restrict__ y_mean,
                               const float* __restrict__ y_var,
                               float* __restrict__ out) {
    int i = blockIdx.x * blockDim.x + threadIdx.x;
    if (i < N * 32)
        out[i] = (y_mean[i] + g_zm[i]) + (y_var[i] + g_zv[i]);
}

// -------------------- launch ------------------------------------------------
extern "C" void kernel_launch(void* const* d_in, const int* in_sizes, int n_in,
                              void* d_out, int out_size) {
    const float* x_mu   = (const float*)d_in[0];
    const float* y_eta  = (const float*)d_in[1];
    const float* y_mean = (const float*)d_in[2];
    const float* y_var  = (const float*)d_in[3];
    const float* X_mean = (const float*)d_in[4];
    const float* X_var  = (const float*)d_in[5];
    const float* Z_mean = (const float*)d_in[6];
    const float* Z_var  = (const float*)d_in[7];
    const float* kMi    = (const float*)d_in[8];
    const float* kVi    = (const float*)d_in[9];
    float* out = (float*)d_out;

    cudaFuncSetAttribute(fusedtc_kernel,
                         cudaFuncAttributeMaxDynamicSharedMemorySize, FUSED_SMEM);
    cudaFuncSetAttribute(lambda_hmma_kernel,
                         cudaFuncAttributeMaxDynamicSharedMemorySize, LAMBDA_SMEM);

    prep_q_kernel<<<(N * 32 + 255) / 256, 256>>>(x_mu, y_eta, y_mean, y_var);
    prep_X_kernel<<<(N * 32 + 255) / 256, 256>>>(X_mean, X_var);
    zsplit_kernel<<<(2 * 32 * N + 255) / 256, 256>>>(Z_mean, Z_var);
    lambda_hmma_kernel<<<dim3(64, 2, 2), 256, LAMBDA_SMEM>>>(kMi, kVi);
    lsplit_kernel<<<(2 * 32 * N + 255) / 256, 256>>>();
    fusedtc_kernel<<<128, 512, FUSED_SMEM>>>();
    combine_kernel<<<(N * 32 + 255) / 256, 256>>>(y_mean, y_var, out);
}

// round 11
// speedup vs baseline: 1.0751x; 1.0751x over previous
#include <cuda_runtime.h>
#include <cuda_fp16.h>
#include <cstdint>

#define N 8192

// -------------------- device scratch ---------------------------------------
__device__ float g_xqm[N * 64];
__device__ float g_xqv[N * 96];
__device__ float g_qnm[N], g_qnv[N], g_Xnm[N], g_Xnv[N];
__device__ float g_LpA0[N * 32], g_LpB0[N * 32];   // Lambda partials (k-halves)
__device__ float g_LpA1[N * 32], g_LpB1[N * 32];
__device__ float g_zm[N * 32], g_zv[N * 32];
__device__ __align__(16) __half g_Xmh[N * 64];          // X hi (phase1 hi-only)
__device__ __align__(16) __half g_Xvh[N * 96];
__device__ __align__(16) __half g_Lth0[32 * N], g_Ltl0[32 * N];
__device__ __align__(16) __half g_Lth1[32 * N], g_Ltl1[32 * N];
__device__ __align__(16) __half g_Zth0[32 * N], g_Ztl0[32 * N];
__device__ __align__(16) __half g_Zth1[32 * N], g_Ztl1[32 * N];

// -------------------- mma helpers (sm_80+ HMMA fp16) ------------------------
__device__ __forceinline__ void mma_f16(float c[4], const uint32_t a[4],
                                        uint32_t b0, uint32_t b1) {
    asm volatile(
        "mma.sync.aligned.m16n8k16.row.col.f32.f16.f16.f32 "
        "{%0,%1,%2,%3}, {%4,%5,%6,%7}, {%8,%9}, {%0,%1,%2,%3};"
        : "+f"(c[0]), "+f"(c[1]), "+f"(c[2]), "+f"(c[3])
        : "r"(a[0]), "r"(a[1]), "r"(a[2]), "r"(a[3]), "r"(b0), "r"(b1));
}
__device__ __forceinline__ uint32_t packhf(float lo, float hi) {
    uint32_t r;
    asm("cvt.rn.f16x2.f32 %0, %1, %2;" : "=r"(r) : "f"(hi), "f"(lo));
    return r;
}
__device__ __forceinline__ float2 up2(uint32_t w) {
    __half2 h = *reinterpret_cast<__half2*>(&w);
    return __half22float2(h);
}
__device__ __forceinline__ uint32_t ldsw(const __half* p) {
    return *(const uint32_t*)p;
}
// group-scoped named barrier: 256 threads of group g
#define GBAR(g) asm volatile("bar.sync %0, 256;" :: "r"(1 + (g)) : "memory")

// -------------------- prep kernels ------------------------------------------
__global__ void prep_q_kernel(const float* __restrict__ x_mu,
                              const float* __restrict__ y_eta,
                              const float* __restrict__ y_mean,
                              const float* __restrict__ y_var) {
    int q = (blockIdx.x * blockDim.x + threadIdx.x) >> 5;
    int lane = threadIdx.x & 31;
    if (q >= N) return;
    float a = x_mu[q * 32 + lane];
    float m = y_mean[q * 32 + lane] + y_var[q * 32 + lane];
    float e = 0.01f * y_eta[(N - 1 - q) * 32 + lane];
    g_xqm[q * 64 + lane] = a;       g_xqm[q * 64 + 32 + lane] = m;
    g_xqv[q * 96 + lane] = a;       g_xqv[q * 96 + 32 + lane] = e;
    g_xqv[q * 96 + 64 + lane] = m;
    float nm = a * a + m * m, nv = nm + e * e;
    #pragma unroll
    for (int o = 16; o; o >>= 1) {
        nm += __shfl_xor_sync(0xffffffffu, nm, o);
        nv += __shfl_xor_sync(0xffffffffu, nv, o);
    }
    if (lane == 0) { g_qnm[q] = nm; g_qnv[q] = nv; }
}

__global__ void prep_X_kernel(const float* __restrict__ Xm,
                              const float* __restrict__ Xv) {
    int i = (blockIdx.x * blockDim.x + threadIdx.x) >> 5;
    int lane = threadIdx.x & 31;
    if (i >= N) return;
    float nm = 0.f, nv = 0.f;
    #pragma unroll
    for (int c = 0; c < 64; c += 32) {
        float v = Xm[(size_t)i * 64 + c + lane];
        nm += v * v;
        g_Xmh[(size_t)i * 64 + c + lane] = __float2half_rn(v);
    }
    #pragma unroll
    for (int c = 0; c < 96; c += 32) {
        float v = Xv[(size_t)i * 96 + c + lane];
        nv += v * v;
        g_Xvh[(size_t)i * 96 + c + lane] = __float2half_rn(v);
    }
    #pragma unroll
    for (int o = 16; o; o >>= 1) {
        nm += __shfl_xor_sync(0xffffffffu, nm, o);
        nv += __shfl_xor_sync(0xffffffffu, nv, o);
    }
    if (lane == 0) { g_Xnm[i] = nm; g_Xnv[i] = nv; }
}

// Z -> transposed fp16 hi/lo [32][N]
__global__ void zsplit_kernel(const float* __restrict__ Z0,
                              const float* __restrict__ Z1) {
    int idx = blockIdx.x * blockDim.x + threadIdx.x;
    if (idx >= 2 * 32 * N) return;
    int t = idx >= 32 * N;
    int j = idx - t * 32 * N;
    int n = j / N, k = j - n * N;
    float v = (t ? Z1 : Z0)[(size_t)k * 32 + n];
    __half h = __float2half_rn(v);
    (t ? g_Zth1 : g_Zth0)[j] = h;
    (t ? g_Ztl1 : g_Ztl0)[j] = __float2half_rn(v - __half2float(h));
}

// -------------------- Lambda = kXX_inv @ Z on HMMA (R9 single-buffer) -------
__global__ __launch_bounds__(256, 2) void lambda_hmma_kernel(
    const float* __restrict__ A0, const float* __restrict__ A1) {
    const int task = blockIdx.y, kh = blockIdx.z;
    const float* A = task ? A1 : A0;
    const __half* Zh = task ? g_Zth1 : g_Zth0;
    const __half* Zl = task ? g_Ztl1 : g_Ztl0;
    float* Lp = task ? (kh ? g_LpB1 : g_LpA1) : (kh ? g_LpB0 : g_LpA0);

    __shared__ __align__(16) uint32_t sAh[128 * 36], sAl[128 * 36];
    __shared__ __align__(16) uint32_t sZh[32 * 36], sZl[32 * 36];

    const int tid = threadIdx.x, lane = tid & 31, w = tid >> 5;
    const int t = lane & 3, qr = lane >> 2;
    const int rb = blockIdx.x * 128;
    const int kb0 = kh * (N / 2);
    const int zn = (tid * 4) >> 5, zw4 = (tid * 4) & 31;

    float4 pa[8];
    uint4 pzh, pzl;
    #pragma unroll
    for (int it = 0; it < 8; it++) {
        int idx = tid + it * 256;
        int r = idx >> 4, c4 = idx & 15;
        pa[it] = *(const float4*)&A[(size_t)(rb + r) * N + kb0 + c4 * 4];
    }
    pzh = ((const uint4*)Zh)[(zn * (N / 2) + kb0 / 2 + zw4) >> 2];
    pzl = ((const uint4*)Zl)[(zn * (N / 2) + kb0 / 2 + zw4) >> 2];

    float zc[4][4];
    #pragma unroll
    for (int i = 0; i < 4; i++)
        #pragma unroll
        for (int j = 0; j < 4; j++) zc[i][j] = 0.f;

    for (int cb = 0; cb < 64; cb++) {
        __syncthreads();
        #pragma unroll
        for (int it = 0; it < 8; it++) {
            int idx = tid + it * 256;
            int r = idx >> 4, c4 = idx & 15;
            float4 v = pa[it];
            uint32_t h0 = packhf(v.x, v.y);
            uint32_t h1 = packhf(v.z, v.w);
            float2 f0 = up2(h0), f1 = up2(h1);
            *(uint2*)&sAh[r * 36 + c4 * 2] = make_uint2(h0, h1);
            *(uint2*)&sAl[r * 36 + c4 * 2] =
                make_uint2(packhf(v.x - f0.x, v.y - f0.y),
                           packhf(v.z - f1.x, v.w - f1.y));
        }
        *(uint4*)&sZh[zn * 36 + zw4] = pzh;
        *(uint4*)&sZl[zn * 36 + zw4] = pzl;
        __syncthreads();

        if (cb < 63) {
            const int ko = kb0 + (cb + 1) * 64;
            #pragma unroll
            for (int it = 0; it < 8; it++) {
                int idx = tid + it * 256;
                int r = idx >> 4, c4 = idx & 15;
                pa[it] = *(const float4*)&A[(size_t)(rb + r) * N + ko + c4 * 4];
            }
            pzh = ((const uint4*)Zh)[(zn * (N / 2) + ko / 2 + zw4) >> 2];
            pzl = ((const uint4*)Zl)[(zn * (N / 2) + ko / 2 + zw4) >> 2];
        }

        #pragma unroll
        for (int kt = 0; kt < 4; kt++) {
            const int kw = kt * 8 + t;
            uint32_t ah[4], al[4];
            ah[0] = sAh[(w * 16 + qr) * 36 + kw];
            ah[1] = sAh[(w * 16 + qr + 8) * 36 + kw];
            ah[2] = sAh[(w * 16 + qr) * 36 + kw + 4];
            ah[3] = sAh[(w * 16 + qr + 8) * 36 + kw + 4];
            al[0] = sAl[(w * 16 + qr) * 36 + kw];
            al[1] = sAl[(w * 16 + qr + 8) * 36 + kw];
            al[2] = sAl[(w * 16 + qr) * 36 + kw + 4];
            al[3] = sAl[(w * 16 + qr + 8) * 36 + kw + 4];
            #pragma unroll
            for (int nt = 0; nt < 4; nt++) {
                const int nc = nt * 8 + qr;
                uint32_t bh0 = sZh[nc * 36 + kw], bh1 = sZh[nc * 36 + kw + 4];
                uint32_t bl0 = sZl[nc * 36 + kw], bl1 = sZl[nc * 36 + kw + 4];
                mma_f16(zc[nt], ah, bh0, bh1);
                mma_f16(zc[nt], ah, bl0, bl1);
                mma_f16(zc[nt], al, bh0, bh1);
            }
        }
    }

    const int row0 = rb + w * 16 + qr;
    #pragma unroll
    for (int nt = 0; nt < 4; nt++) {
        const int col = nt * 8 + 2 * t;
        Lp[(size_t)row0 * 32 + col]           = zc[nt][0];
        Lp[(size_t)row0 * 32 + col + 1]       = zc[nt][1];
        Lp[(size_t)(row0 + 8) * 32 + col]     = zc[nt][2];
        Lp[(size_t)(row0 + 8) * 32 + col + 1] = zc[nt][3];
    }
}

// Lambda partial sums -> transposed fp16 hi/lo [32][N]
__global__ void lsplit_kernel() {
    int idx = blockIdx.x * blockDim.x + threadIdx.x;
    if (idx >= 2 * 32 * N) return;
    int t = idx >= 32 * N;
    int j = idx - t * 32 * N;
    int n = j / N, k = j - n * N;
    size_t src = (size_t)k * 32 + n;
    float v = (t ? g_LpA1 : g_LpA0)[src] + (t ? g_LpB1 : g_LpB0)[src];
    __half h = __float2half_rn(v);
    (t ? g_Lth1 : g_Lth0)[j] = h;
    (t ? g_Ltl1 : g_Ltl0)[j] = __float2half_rn(v - __half2float(h));
}

// -------------------- fused HMMA kernel (phase2 2-MMA: Ph.Lh + Ph.Ll) -------
template <int D>
__device__ void ftc(char* smraw, const __half* Xh,
                    const float* Qg, const __half* Lth,
                    const __half* Ltl, const float* Xn,
                    const float* Qn, float* Zg, int qb) {
    constexpr int QS = D + 8;
    __half* sQh  = (__half*)smraw;
    __half* sXhB = sQh + 128 * QS;
    __half* sLhB = sXhB + 2 * 64 * QS;
    __half* sLlB = sLhB + 2 * 32 * 72;
    float* sXnB = (float*)(sLlB + 2 * 32 * 72);
    float* sRed = (float*)sXhB;            // reused after the chunk loop

    const int tid = threadIdx.x;
    const int g = tid >> 8, wtid = tid & 255;
    const int lane = tid & 31, w = wtid >> 5;
    const int t = lane & 3, qr = lane >> 2;
    const int wq0 = w * 16;
    __half* sXh = sXhB + g * 64 * QS;
    __half* sLh = sLhB + g * 32 * 72;
    __half* sLl = sLlB + g * 32 * 72;
    float* sXn = sXnB + g * 64;

    // Q -> SMEM fp16 hi (all 512 threads), then full-CTA sync
    for (int i = tid; i < 128 * D; i += 512) {
        int r = i / D, c = i - r * D;
        sQh[r * QS + c] = __float2half_rn(Qg[(size_t)(qb + r) * D + c]);
    }
    __syncthreads();
    const float qn0 = Qn[qb + wq0 + qr];
    const float qn1 = Qn[qb + wq0 + qr + 8];

    float zc[4][4];
    #pragma unroll
    for (int i = 0; i < 4; i++)
        #pragma unroll
        for (int j = 0; j < 4; j++) zc[i][j] = 0.f;

    for (int it = 0; it < 64; it++) {
        const int xb = (2 * it + g) * 64;
        // ---- stage this group's chunk ----
        #pragma unroll
        for (int i = wtid; i < 64 * (D / 4); i += 256) {
            int r = i / (D / 4), p = i - r * (D / 4);
            uint2 vh = ((const uint2*)Xh)[(size_t)(xb + r) * (D / 4) + p];
            *(uint2*)(sXh + r * QS + p * 4) = vh;
        }
        #pragma unroll
        for (int i = wtid; i < 32 * 16; i += 256) {
            int n = i >> 4, p = i & 15;
            uint2 vh = ((const uint2*)Lth)[(size_t)n * (N / 4) + xb / 4 + p];
            uint2 vl = ((const uint2*)Ltl)[(size_t)n * (N / 4) + xb / 4 + p];
            *(uint2*)(sLh + n * 72 + p * 4) = vh;
            *(uint2*)(sLl + n * 72 + p * 4) = vl;
        }
        if (wtid < 64) sXn[wtid] = Xn[xb + wtid];
        GBAR(g);

        // ---- phase 1: D1[16q x 64x] = Qh . Xh^T ----
        float c1[8][4];
        #pragma unroll
        for (int i = 0; i < 8; i++)
            #pragma unroll
            for (int j = 0; j < 4; j++) c1[i][j] = 0.f;

        #pragma unroll
        for (int kt = 0; kt < D / 16; kt++) {
            const int k0 = kt * 16 + 2 * t;
            uint32_t ah[4];
            ah[0] = ldsw(sQh + (wq0 + qr) * QS + k0);
            ah[1] = ldsw(sQh + (wq0 + qr + 8) * QS + k0);
            ah[2] = ldsw(sQh + (wq0 + qr) * QS + k0 + 8);
            ah[3] = ldsw(sQh + (wq0 + qr + 8) * QS + k0 + 8);
            #pragma unroll
            for (int nt = 0; nt < 8; nt++) {
                const int xr = nt * 8 + qr;
                uint32_t bh0 = ldsw(sXh + xr * QS + k0);
                uint32_t bh1 = ldsw(sXh + xr * QS + k0 + 8);
                mma_f16(c1[nt], ah, bh0, bh1);
            }
        }

        // ---- epilogue: exp -> P hi fragments only ----
        uint32_t Ph[4][4];
        #pragma unroll
        for (int kt2 = 0; kt2 < 4; kt2++) {
            #pragma unroll
            for (int s = 0; s < 2; s++) {
                const int nt = 2 * kt2 + s;
                const int x0 = nt * 8 + 2 * t;
                float xna = sXn[x0], xnb = sXn[x0 + 1];
                float p0 = __expf(-0.0078125f * fmaxf(qn0 + xna - 2.f * c1[nt][0], 0.f));
                float p1 = __expf(-0.0078125f * fmaxf(qn0 + xnb - 2.f * c1[nt][1], 0.f));
                float p2 = __expf(-0.0078125f * fmaxf(qn1 + xna - 2.f * c1[nt][2], 0.f));
                float p3 = __expf(-0.0078125f * fmaxf(qn1 + xnb - 2.f * c1[nt][3], 0.f));
                Ph[kt2][2 * s]     = packhf(p0, p1);
                Ph[kt2][2 * s + 1] = packhf(p2, p3);
            }
        }

        // ---- phase 2: z += Ph . (Lh + Ll)^T  (2 MMAs) ----
        #pragma unroll
        for (int kt2 = 0; kt2 < 4; kt2++) {
            const int k0 = kt2 * 16 + 2 * t;
            #pragma unroll
            for (int nt = 0; nt < 4; nt++) {
                const int nc = nt * 8 + qr;
                uint32_t bh0 = ldsw(sLh + nc * 72 + k0);
                uint32_t bh1 = ldsw(sLh + nc * 72 + k0 + 8);
                uint32_t bl0 = ldsw(sLl + nc * 72 + k0);
                uint32_t bl1 = ldsw(sLl + nc * 72 + k0 + 8);
                mma_f16(zc[nt], Ph[kt2], bh0, bh1);
                mma_f16(zc[nt], Ph[kt2], bl0, bl1);
            }
        }
        GBAR(g);
    }

    // ---- combine the two x-half partial sums (full-CTA sync) ----
    __syncthreads();
    const int row0 = wq0 + qr;
    if (g == 1) {
        #pragma unroll
        for (int nt = 0; nt < 4; nt++) {
            const int col = nt * 8 + 2 * t;
            sRed[row0 * 33 + col]           = zc[nt][0];
            sRed[row0 * 33 + col + 1]       = zc[nt][1];
            sRed[(row0 + 8) * 33 + col]     = zc[nt][2];
            sRed[(row0 + 8) * 33 + col + 1] = zc[nt][3];
        }
    }
    __syncthreads();
    if (g == 0) {
        #pragma unroll
        for (int nt = 0; nt < 4; nt++) {
            const int col = nt * 8 + 2 * t;
            float v0 = zc[nt][0] + sRed[row0 * 33 + col];
            float v1 = zc[nt][1] + sRed[row0 * 33 + col + 1];
            float v2 = zc[nt][2] + sRed[(row0 + 8) * 33 + col];
            float v3 = zc[nt][3] + sRed[(row0 + 8) * 33 + col + 1];
            Zg[(size_t)(qb + row0) * 32 + col]           = v0;
            Zg[(size_t)(qb + row0) * 32 + col + 1]       = v1;
            Zg[(size_t)(qb + row0 + 8) * 32 + col]       = v2;
            Zg[(size_t)(qb + row0 + 8) * 32 + col + 1]   = v3;
        }
    }
}

// D=96: (128*104 + 2*64*104 + 2*2*32*72) half + 2*64 f32 = 71680 + 512
#define FUSED_SMEM 72704

__global__ __launch_bounds__(512, 1) void fusedtc_kernel() {
    extern __shared__ char sm[];
    int task = blockIdx.x >> 6;
    int qb   = (blockIdx.x & 63) * 128;
    if (task == 0)
        ftc<64>(sm, g_Xmh, g_xqm, g_Lth0, g_Ltl0, g_Xnm, g_qnm, g_zm, qb);
    else
        ftc<96>(sm, g_Xvh, g_xqv, g_Lth1, g_Ltl1, g_Xnv, g_qnv, g_zv, qb);
}

// -------------------- combine ----------------------------------------------
__global__ void combine_kernel(const float* __restrict__ y_mean,
                               const float* __restrict__ y_var,
                               float* __restrict__ out) {
    int i = blockIdx.x * blockDim.x + threadIdx.x;
    if (i < N * 32)
        out[i] = (y_mean[i] + g_zm[i]) + (y_var[i] + g_zv[i]);
}

// -------------------- launch ------------------------------------------------
extern "C" void kernel_launch(void* const* d_in, const int* in_sizes, int n_in,
                              void* d_out, int out_size) {
    const float* x_mu   = (const float*)d_in[0];
    const float* y_eta  = (const float*)d_in[1];
    const float* y_mean = (const float*)d_in[2];
    const float* y_var  = (const float*)d_in[3];
    const float* X_mean = (const float*)d_in[4];
    const float* X_var  = (const float*)d_in[5];
    const float* Z_mean = (const float*)d_in[6];
    const float* Z_var  = (const float*)d_in[7];
    const float* kMi    = (const float*)d_in[8];
    const float* kVi    = (const float*)d_in[9];
    float* out = (float*)d_out;

    cudaFuncSetAttribute(fusedtc_kernel,
                         cudaFuncAttributeMaxDynamicSharedMemorySize, FUSED_SMEM);

    prep_q_kernel<<<(N * 32 + 255) / 256, 256>>>(x_mu, y_eta, y_mean, y_var);
    prep_X_kernel<<<(N * 32 + 255) / 256, 256>>>(X_mean, X_var);
    zsplit_kernel<<<(2 * 32 * N + 255) / 256, 256>>>(Z_mean, Z_var);
    lambda_hmma_kernel<<<dim3(64, 2, 2), 256>>>(kMi, kVi);
    lsplit_kernel<<<(2 * 32 * N + 255) / 256, 256>>>();
    fusedtc_kernel<<<128, 512, FUSED_SMEM>>>();
    combine_kernel<<<(N * 32 + 255) / 256, 256>>>(y_mean, y_var, out);
}

// round 12
// speedup vs baseline: 1.2171x; 1.1320x over previous
#include <cuda_runtime.h>
#include <cuda_fp16.h>
#include <cstdint>

#define N 8192

// -------------------- device scratch ---------------------------------------
__device__ float g_xqm[N * 64];
__device__ float g_xqv[N * 96];
__device__ float g_qnm[N], g_qnv[N], g_Xnm[N], g_Xnv[N];
__device__ float g_LpA0[N * 32], g_LpB0[N * 32];   // Lambda partials (k-halves)
__device__ float g_LpA1[N * 32], g_LpB1[N * 32];
__device__ float g_zm[N * 32], g_zv[N * 32];
__device__ __align__(16) __half g_Xmh[N * 64];          // X hi (phase1 hi-only)
__device__ __align__(16) __half g_Xvh[N * 96];
__device__ __align__(16) __half g_Lth0[32 * N];         // Lambda^T hi only
__device__ __align__(16) __half g_Lth1[32 * N];
__device__ __align__(16) __half g_Zth0[32 * N], g_Ztl0[32 * N];
__device__ __align__(16) __half g_Zth1[32 * N], g_Ztl1[32 * N];

// -------------------- mma helpers (sm_80+ HMMA fp16) ------------------------
__device__ __forceinline__ void mma_f16(float c[4], const uint32_t a[4],
                                        uint32_t b0, uint32_t b1) {
    asm volatile(
        "mma.sync.aligned.m16n8k16.row.col.f32.f16.f16.f32 "
        "{%0,%1,%2,%3}, {%4,%5,%6,%7}, {%8,%9}, {%0,%1,%2,%3};"
        : "+f"(c[0]), "+f"(c[1]), "+f"(c[2]), "+f"(c[3])
        : "r"(a[0]), "r"(a[1]), "r"(a[2]), "r"(a[3]), "r"(b0), "r"(b1));
}
__device__ __forceinline__ uint32_t packhf(float lo, float hi) {
    uint32_t r;
    asm("cvt.rn.f16x2.f32 %0, %1, %2;" : "=r"(r) : "f"(hi), "f"(lo));
    return r;
}
__device__ __forceinline__ float2 up2(uint32_t w) {
    __half2 h = *reinterpret_cast<__half2*>(&w);
    return __half22float2(h);
}
__device__ __forceinline__ uint32_t ldsw(const __half* p) {
    return *(const uint32_t*)p;
}
// group-scoped named barrier: 256 threads of group g
#define GBAR(g) asm volatile("bar.sync %0, 256;" :: "r"(1 + (g)) : "memory")

// -------------------- prep kernels ------------------------------------------
__global__ void prep_q_kernel(const float* __restrict__ x_mu,
                              const float* __restrict__ y_eta,
                              const float* __restrict__ y_mean,
                              const float* __restrict__ y_var) {
    int q = (blockIdx.x * blockDim.x + threadIdx.x) >> 5;
    int lane = threadIdx.x & 31;
    if (q >= N) return;
    float a = x_mu[q * 32 + lane];
    float m = y_mean[q * 32 + lane] + y_var[q * 32 + lane];
    float e = 0.01f * y_eta[(N - 1 - q) * 32 + lane];
    g_xqm[q * 64 + lane] = a;       g_xqm[q * 64 + 32 + lane] = m;
    g_xqv[q * 96 + lane] = a;       g_xqv[q * 96 + 32 + lane] = e;
    g_xqv[q * 96 + 64 + lane] = m;
    float nm = a * a + m * m, nv = nm + e * e;
    #pragma unroll
    for (int o = 16; o; o >>= 1) {
        nm += __shfl_xor_sync(0xffffffffu, nm, o);
        nv += __shfl_xor_sync(0xffffffffu, nv, o);
    }
    if (lane == 0) { g_qnm[q] = nm; g_qnv[q] = nv; }
}

__global__ void prep_X_kernel(const float* __restrict__ Xm,
                              const float* __restrict__ Xv) {
    int i = (blockIdx.x * blockDim.x + threadIdx.x) >> 5;
    int lane = threadIdx.x & 31;
    if (i >= N) return;
    float nm = 0.f, nv = 0.f;
    #pragma unroll
    for (int c = 0; c < 64; c += 32) {
        float v = Xm[(size_t)i * 64 + c + lane];
        nm += v * v;
        g_Xmh[(size_t)i * 64 + c + lane] = __float2half_rn(v);
    }
    #pragma unroll
    for (int c = 0; c < 96; c += 32) {
        float v = Xv[(size_t)i * 96 + c + lane];
        nv += v * v;
        g_Xvh[(size_t)i * 96 + c + lane] = __float2half_rn(v);
    }
    #pragma unroll
    for (int o = 16; o; o >>= 1) {
        nm += __shfl_xor_sync(0xffffffffu, nm, o);
        nv += __shfl_xor_sync(0xffffffffu, nv, o);
    }
    if (lane == 0) { g_Xnm[i] = nm; g_Xnv[i] = nv; }
}

// Z -> transposed fp16 hi/lo [32][N]
__global__ void zsplit_kernel(const float* __restrict__ Z0,
                              const float* __restrict__ Z1) {
    int idx = blockIdx.x * blockDim.x + threadIdx.x;
    if (idx >= 2 * 32 * N) return;
    int t = idx >= 32 * N;
    int j = idx - t * 32 * N;
    int n = j / N, k = j - n * N;
    float v = (t ? Z1 : Z0)[(size_t)k * 32 + n];
    __half h = __float2half_rn(v);
    (t ? g_Zth1 : g_Zth0)[j] = h;
    (t ? g_Ztl1 : g_Ztl0)[j] = __float2half_rn(v - __half2float(h));
}

// -------------------- Lambda = kXX_inv @ Z on HMMA (A hi-only, 2-MMA) -------
__global__ __launch_bounds__(256, 2) void lambda_hmma_kernel(
    const float* __restrict__ A0, const float* __restrict__ A1) {
    const int task = blockIdx.y, kh = blockIdx.z;
    const float* A = task ? A1 : A0;
    const __half* Zh = task ? g_Zth1 : g_Zth0;
    const __half* Zl = task ? g_Ztl1 : g_Ztl0;
    float* Lp = task ? (kh ? g_LpB1 : g_LpA1) : (kh ? g_LpB0 : g_LpA0);

    __shared__ __align__(16) uint32_t sAh[128 * 36];
    __shared__ __align__(16) uint32_t sZh[32 * 36], sZl[32 * 36];

    const int tid = threadIdx.x, lane = tid & 31, w = tid >> 5;
    const int t = lane & 3, qr = lane >> 2;
    const int rb = blockIdx.x * 128;
    const int kb0 = kh * (N / 2);
    const int zn = (tid * 4) >> 5, zw4 = (tid * 4) & 31;

    float4 pa[8];
    uint4 pzh, pzl;
    #pragma unroll
    for (int it = 0; it < 8; it++) {
        int idx = tid + it * 256;
        int r = idx >> 4, c4 = idx & 15;
        pa[it] = *(const float4*)&A[(size_t)(rb + r) * N + kb0 + c4 * 4];
    }
    pzh = ((const uint4*)Zh)[(zn * (N / 2) + kb0 / 2 + zw4) >> 2];
    pzl = ((const uint4*)Zl)[(zn * (N / 2) + kb0 / 2 + zw4) >> 2];

    float zc[4][4];
    #pragma unroll
    for (int i = 0; i < 4; i++)
        #pragma unroll
        for (int j = 0; j < 4; j++) zc[i][j] = 0.f;

    for (int cb = 0; cb < 64; cb++) {
        __syncthreads();
        #pragma unroll
        for (int it = 0; it < 8; it++) {
            int idx = tid + it * 256;
            int r = idx >> 4, c4 = idx & 15;
            float4 v = pa[it];
            *(uint2*)&sAh[r * 36 + c4 * 2] =
                make_uint2(packhf(v.x, v.y), packhf(v.z, v.w));
        }
        *(uint4*)&sZh[zn * 36 + zw4] = pzh;
        *(uint4*)&sZl[zn * 36 + zw4] = pzl;
        __syncthreads();

        if (cb < 63) {
            const int ko = kb0 + (cb + 1) * 64;
            #pragma unroll
            for (int it = 0; it < 8; it++) {
                int idx = tid + it * 256;
                int r = idx >> 4, c4 = idx & 15;
                pa[it] = *(const float4*)&A[(size_t)(rb + r) * N + ko + c4 * 4];
            }
            pzh = ((const uint4*)Zh)[(zn * (N / 2) + ko / 2 + zw4) >> 2];
            pzl = ((const uint4*)Zl)[(zn * (N / 2) + ko / 2 + zw4) >> 2];
        }

        #pragma unroll
        for (int kt = 0; kt < 4; kt++) {
            const int kw = kt * 8 + t;
            uint32_t ah[4];
            ah[0] = sAh[(w * 16 + qr) * 36 + kw];
            ah[1] = sAh[(w * 16 + qr + 8) * 36 + kw];
            ah[2] = sAh[(w * 16 + qr) * 36 + kw + 4];
            ah[3] = sAh[(w * 16 + qr + 8) * 36 + kw + 4];
            #pragma unroll
            for (int nt = 0; nt < 4; nt++) {
                const int nc = nt * 8 + qr;
                uint32_t bh0 = sZh[nc * 36 + kw], bh1 = sZh[nc * 36 + kw + 4];
                uint32_t bl0 = sZl[nc * 36 + kw], bl1 = sZl[nc * 36 + kw + 4];
                mma_f16(zc[nt], ah, bh0, bh1);
                mma_f16(zc[nt], ah, bl0, bl1);
            }
        }
    }

    const int row0 = rb + w * 16 + qr;
    #pragma unroll
    for (int nt = 0; nt < 4; nt++) {
        const int col = nt * 8 + 2 * t;
        Lp[(size_t)row0 * 32 + col]           = zc[nt][0];
        Lp[(size_t)row0 * 32 + col + 1]       = zc[nt][1];
        Lp[(size_t)(row0 + 8) * 32 + col]     = zc[nt][2];
        Lp[(size_t)(row0 + 8) * 32 + col + 1] = zc[nt][3];
    }
}

// Lambda partial sums -> transposed fp16 hi [32][N]
__global__ void lsplit_kernel() {
    int idx = blockIdx.x * blockDim.x + threadIdx.x;
    if (idx >= 2 * 32 * N) return;
    int t = idx >= 32 * N;
    int j = idx - t * 32 * N;
    int n = j / N, k = j - n * N;
    size_t src = (size_t)k * 32 + n;
    float v = (t ? g_LpA1 : g_LpA0)[src] + (t ? g_LpB1 : g_LpB0)[src];
    (t ? g_Lth1 : g_Lth0)[j] = __float2half_rn(v);
}

// -------------------- fused HMMA kernel (phase2 1-MMA: Ph.Lh) ---------------
template <int D>
__device__ void ftc(char* smraw, const __half* Xh,
                    const float* Qg, const __half* Lth,
                    const float* Xn, const float* Qn, float* Zg, int qb) {
    constexpr int QS = D + 8;
    __half* sQh  = (__half*)smraw;
    __half* sXhB = sQh + 128 * QS;
    __half* sLhB = sXhB + 2 * 64 * QS;
    float* sXnB = (float*)(sLhB + 2 * 32 * 72);
    float* sRed = (float*)sXhB;            // reused after the chunk loop

    const int tid = threadIdx.x;
    const int g = tid >> 8, wtid = tid & 255;
    const int lane = tid & 31, w = wtid >> 5;
    const int t = lane & 3, qr = lane >> 2;
    const int wq0 = w * 16;
    __half* sXh = sXhB + g * 64 * QS;
    __half* sLh = sLhB + g * 32 * 72;
    float* sXn = sXnB + g * 64;

    // Q -> SMEM fp16 hi (all 512 threads), then full-CTA sync
    for (int i = tid; i < 128 * D; i += 512) {
        int r = i / D, c = i - r * D;
        sQh[r * QS + c] = __float2half_rn(Qg[(size_t)(qb + r) * D + c]);
    }
    __syncthreads();
    const float qn0 = Qn[qb + wq0 + qr];
    const float qn1 = Qn[qb + wq0 + qr + 8];

    float zc[4][4];
    #pragma unroll
    for (int i = 0; i < 4; i++)
        #pragma unroll
        for (int j = 0; j < 4; j++) zc[i][j] = 0.f;

    for (int it = 0; it < 64; it++) {
        const int xb = (2 * it + g) * 64;
        // ---- stage this group's chunk ----
        #pragma unroll
        for (int i = wtid; i < 64 * (D / 4); i += 256) {
            int r = i / (D / 4), p = i - r * (D / 4);
            uint2 vh = ((const uint2*)Xh)[(size_t)(xb + r) * (D / 4) + p];
            *(uint2*)(sXh + r * QS + p * 4) = vh;
        }
        #pragma unroll
        for (int i = wtid; i < 32 * 16; i += 256) {
            int n = i >> 4, p = i & 15;
            uint2 vh = ((const uint2*)Lth)[(size_t)n * (N / 4) + xb / 4 + p];
            *(uint2*)(sLh + n * 72 + p * 4) = vh;
        }
        if (wtid < 64) sXn[wtid] = Xn[xb + wtid];
        GBAR(g);

        // ---- phase 1: D1[16q x 64x] = Qh . Xh^T ----
        float c1[8][4];
        #pragma unroll
        for (int i = 0; i < 8; i++)
            #pragma unroll
            for (int j = 0; j < 4; j++) c1[i][j] = 0.f;

        #pragma unroll
        for (int kt = 0; kt < D / 16; kt++) {
            const int k0 = kt * 16 + 2 * t;
            uint32_t ah[4];
            ah[0] = ldsw(sQh + (wq0 + qr) * QS + k0);
            ah[1] = ldsw(sQh + (wq0 + qr + 8) * QS + k0);
            ah[2] = ldsw(sQh + (wq0 + qr) * QS + k0 + 8);
            ah[3] = ldsw(sQh + (wq0 + qr + 8) * QS + k0 + 8);
            #pragma unroll
            for (int nt = 0; nt < 8; nt++) {
                const int xr = nt * 8 + qr;
                uint32_t bh0 = ldsw(sXh + xr * QS + k0);
                uint32_t bh1 = ldsw(sXh + xr * QS + k0 + 8);
                mma_f16(c1[nt], ah, bh0, bh1);
            }
        }

        // ---- epilogue: exp -> P hi fragments ----
        uint32_t Ph[4][4];
        #pragma unroll
        for (int kt2 = 0; kt2 < 4; kt2++) {
            #pragma unroll
            for (int s = 0; s < 2; s++) {
                const int nt = 2 * kt2 + s;
                const int x0 = nt * 8 + 2 * t;
                float xna = sXn[x0], xnb = sXn[x0 + 1];
                float p0 = __expf(-0.0078125f * fmaxf(qn0 + xna - 2.f * c1[nt][0], 0.f));
                float p1 = __expf(-0.0078125f * fmaxf(qn0 + xnb - 2.f * c1[nt][1], 0.f));
                float p2 = __expf(-0.0078125f * fmaxf(qn1 + xna - 2.f * c1[nt][2], 0.f));
                float p3 = __expf(-0.0078125f * fmaxf(qn1 + xnb - 2.f * c1[nt][3], 0.f));
                Ph[kt2][2 * s]     = packhf(p0, p1);
                Ph[kt2][2 * s + 1] = packhf(p2, p3);
            }
        }

        // ---- phase 2: z += Ph . Lh^T  (1 MMA) ----
        #pragma unroll
        for (int kt2 = 0; kt2 < 4; kt2++) {
            const int k0 = kt2 * 16 + 2 * t;
            #pragma unroll
            for (int nt = 0; nt < 4; nt++) {
                const int nc = nt * 8 + qr;
                uint32_t bh0 = ldsw(sLh + nc * 72 + k0);
                uint32_t bh1 = ldsw(sLh + nc * 72 + k0 + 8);
                mma_f16(zc[nt], Ph[kt2], bh0, bh1);
            }
        }
        GBAR(g);
    }

    // ---- combine the two x-half partial sums (full-CTA sync) ----
    __syncthreads();
    const int row0 = wq0 + qr;
    if (g == 1) {
        #pragma unroll
        for (int nt = 0; nt < 4; nt++) {
            const int col = nt * 8 + 2 * t;
            sRed[row0 * 33 + col]           = zc[nt][0];
            sRed[row0 * 33 + col + 1]       = zc[nt][1];
            sRed[(row0 + 8) * 33 + col]     = zc[nt][2];
            sRed[(row0 + 8) * 33 + col + 1] = zc[nt][3];
        }
    }
    __syncthreads();
    if (g == 0) {
        #pragma unroll
        for (int nt = 0; nt < 4; nt++) {
            const int col = nt * 8 + 2 * t;
            float v0 = zc[nt][0] + sRed[row0 * 33 + col];
            float v1 = zc[nt][1] + sRed[row0 * 33 + col + 1];
            float v2 = zc[nt][2] + sRed[(row0 + 8) * 33 + col];
            float v3 = zc[nt][3] + sRed[(row0 + 8) * 33 + col + 1];
            Zg[(size_t)(qb + row0) * 32 + col]           = v0;
            Zg[(size_t)(qb + row0) * 32 + col + 1]       = v1;
            Zg[(size_t)(qb + row0 + 8) * 32 + col]       = v2;
            Zg[(size_t)(qb + row0 + 8) * 32 + col + 1]   = v3;
        }
    }
}

// D=96: (128*104 + 2*64*104 + 2*32*72) half + 2*64 f32 = 62464 + 512
#define FUSED_SMEM 63488

__global__ __launch_bounds__(512, 1) void fusedtc_kernel() {
    extern __shared__ char sm[];
    int task = blockIdx.x >> 6;
    int qb   = (blockIdx.x & 63) * 128;
    if (task == 0)
        ftc<64>(sm, g_Xmh, g_xqm, g_Lth0, g_Xnm, g_qnm, g_zm, qb);
    else
        ftc<96>(sm, g_Xvh, g_xqv, g_Lth1, g_Xnv, g_qnv, g_zv, qb);
}

// -------------------- combine ----------------------------------------------
__global__ void combine_kernel(const float* __restrict__ y_mean,
                               const float* __restrict__ y_var,
                               float* __restrict__ out) {
    int i = blockIdx.x * blockDim.x + threadIdx.x;
    if (i < N * 32)
        out[i] = (y_mean[i] + g_zm[i]) + (y_var[i] + g_zv[i]);
}

// -------------------- launch ------------------------------------------------
extern "C" void kernel_launch(void* const* d_in, const int* in_sizes, int n_in,
                              void* d_out, int out_size) {
    const float* x_mu   = (const float*)d_in[0];
    const float* y_eta  = (const float*)d_in[1];
    const float* y_mean = (const float*)d_in[2];
    const float* y_var  = (const float*)d_in[3];
    const float* X_mean = (const float*)d_in[4];
    const float* X_var  = (const float*)d_in[5];
    const float* Z_mean = (const float*)d_in[6];
    const float* Z_var  = (const float*)d_in[7];
    const float* kMi    = (const float*)d_in[8];
    const float* kVi    = (const float*)d_in[9];
    float* out = (float*)d_out;

    cudaFuncSetAttribute(fusedtc_kernel,
                         cudaFuncAttributeMaxDynamicSharedMemorySize, FUSED_SMEM);

    prep_q_kernel<<<(N * 32 + 255) / 256, 256>>>(x_mu, y_eta, y_mean, y_var);
    prep_X_kernel<<<(N * 32 + 255) / 256, 256>>>(X_mean, X_var);
    zsplit_kernel<<<(2 * 32 * N + 255) / 256, 256>>>(Z_mean, Z_var);
    lambda_hmma_kernel<<<dim3(64, 2, 2), 256>>>(kMi, kVi);
    lsplit_kernel<<<(2 * 32 * N + 255) / 256, 256>>>();
    fusedtc_kernel<<<128, 512, FUSED_SMEM>>>();
    combine_kernel<<<(N * 32 + 255) / 256, 256>>>(y_mean, y_var, out);
}

// round 13
// speedup vs baseline: 1.3003x; 1.0684x over previous
#include <cuda_runtime.h>
#include <cuda_fp16.h>
#include <cstdint>

#define N 8192

// -------------------- device scratch ---------------------------------------
__device__ float g_xqm[N * 64];
__device__ float g_xqv[N * 96];
__device__ float g_qnm[N], g_qnv[N], g_Xnm[N], g_Xnv[N];
__device__ float g_LpA0[N * 32], g_LpB0[N * 32];   // Lambda partials (k-halves)
__device__ float g_LpA1[N * 32], g_LpB1[N * 32];
__device__ float g_zm[N * 32], g_zv[N * 32];
__device__ __align__(16) __half g_Xmh[N * 64];          // X hi (phase1 hi-only)
__device__ __align__(16) __half g_Xvh[N * 96];
__device__ __align__(16) __half g_Lth0[32 * N];         // Lambda^T hi only
__device__ __align__(16) __half g_Lth1[32 * N];
__device__ __align__(16) __half g_Zth0[32 * N];         // Z^T hi only
__device__ __align__(16) __half g_Zth1[32 * N];

// -------------------- mma / ldmatrix helpers --------------------------------
__device__ __forceinline__ void mma_f16(float c[4], const uint32_t a[4],
                                        uint32_t b0, uint32_t b1) {
    asm volatile(
        "mma.sync.aligned.m16n8k16.row.col.f32.f16.f16.f32 "
        "{%0,%1,%2,%3}, {%4,%5,%6,%7}, {%8,%9}, {%0,%1,%2,%3};"
        : "+f"(c[0]), "+f"(c[1]), "+f"(c[2]), "+f"(c[3])
        : "r"(a[0]), "r"(a[1]), "r"(a[2]), "r"(a[3]), "r"(b0), "r"(b1));
}
__device__ __forceinline__ uint32_t packhf(float lo, float hi) {
    uint32_t r;
    asm("cvt.rn.f16x2.f32 %0, %1, %2;" : "=r"(r) : "f"(hi), "f"(lo));
    return r;
}
__device__ __forceinline__ uint32_t s2u(const void* p) {
    return (uint32_t)__cvta_generic_to_shared(p);
}
__device__ __forceinline__ void ldsm4(uint32_t* r, uint32_t addr) {
    asm volatile("ldmatrix.sync.aligned.m8n8.x4.shared.b16 {%0,%1,%2,%3}, [%4];"
                 : "=r"(r[0]), "=r"(r[1]), "=r"(r[2]), "=r"(r[3]) : "r"(addr));
}
// group-scoped named barrier: 256 threads of group g
#define GBAR(g) asm volatile("bar.sync %0, 256;" :: "r"(1 + (g)) : "memory")

// -------------------- prep kernels ------------------------------------------
__global__ void prep_q_kernel(const float* __restrict__ x_mu,
                              const float* __restrict__ y_eta,
                              const float* __restrict__ y_mean,
                              const float* __restrict__ y_var) {
    int q = (blockIdx.x * blockDim.x + threadIdx.x) >> 5;
    int lane = threadIdx.x & 31;
    if (q >= N) return;
    float a = x_mu[q * 32 + lane];
    float m = y_mean[q * 32 + lane] + y_var[q * 32 + lane];
    float e = 0.01f * y_eta[(N - 1 - q) * 32 + lane];
    g_xqm[q * 64 + lane] = a;       g_xqm[q * 64 + 32 + lane] = m;
    g_xqv[q * 96 + lane] = a;       g_xqv[q * 96 + 32 + lane] = e;
    g_xqv[q * 96 + 64 + lane] = m;
    float nm = a * a + m * m, nv = nm + e * e;
    #pragma unroll
    for (int o = 16; o; o >>= 1) {
        nm += __shfl_xor_sync(0xffffffffu, nm, o);
        nv += __shfl_xor_sync(0xffffffffu, nv, o);
    }
    if (lane == 0) { g_qnm[q] = nm; g_qnv[q] = nv; }
}

__global__ void prep_X_kernel(const float* __restrict__ Xm,
                              const float* __restrict__ Xv) {
    int i = (blockIdx.x * blockDim.x + threadIdx.x) >> 5;
    int lane = threadIdx.x & 31;
    if (i >= N) return;
    float nm = 0.f, nv = 0.f;
    #pragma unroll
    for (int c = 0; c < 64; c += 32) {
        float v = Xm[(size_t)i * 64 + c + lane];
        nm += v * v;
        g_Xmh[(size_t)i * 64 + c + lane] = __float2half_rn(v);
    }
    #pragma unroll
    for (int c = 0; c < 96; c += 32) {
        float v = Xv[(size_t)i * 96 + c + lane];
        nv += v * v;
        g_Xvh[(size_t)i * 96 + c + lane] = __float2half_rn(v);
    }
    #pragma unroll
    for (int o = 16; o; o >>= 1) {
        nm += __shfl_xor_sync(0xffffffffu, nm, o);
        nv += __shfl_xor_sync(0xffffffffu, nv, o);
    }
    if (lane == 0) { g_Xnm[i] = nm; g_Xnv[i] = nv; }
}

// Z -> transposed fp16 hi [32][N]
__global__ void zsplit_kernel(const float* __restrict__ Z0,
                              const float* __restrict__ Z1) {
    int idx = blockIdx.x * blockDim.x + threadIdx.x;
    if (idx >= 2 * 32 * N) return;
    int t = idx >= 32 * N;
    int j = idx - t * 32 * N;
    int n = j / N, k = j - n * N;
    float v = (t ? Z1 : Z0)[(size_t)k * 32 + n];
    (t ? g_Zth1 : g_Zth0)[j] = __float2half_rn(v);
}

// -------------------- Lambda = kXX_inv @ Z on HMMA (hi-only, 1-MMA) ---------
__global__ __launch_bounds__(256, 2) void lambda_hmma_kernel(
    const float* __restrict__ A0, const float* __restrict__ A1) {
    const int task = blockIdx.y, kh = blockIdx.z;
    const float* A = task ? A1 : A0;
    const __half* Zh = task ? g_Zth1 : g_Zth0;
    float* Lp = task ? (kh ? g_LpB1 : g_LpA1) : (kh ? g_LpB0 : g_LpA0);

    __shared__ __align__(16) uint32_t sAh[128 * 36];
    __shared__ __align__(16) uint32_t sZh[32 * 36];

    const int tid = threadIdx.x, lane = tid & 31, w = tid >> 5;
    const int t = lane & 3, qr = lane >> 2;
    const int rb = blockIdx.x * 128;
    const int kb0 = kh * (N / 2);
    const int zn = (tid * 4) >> 5, zw4 = (tid * 4) & 31;

    float4 pa[8];
    uint4 pzh;
    #pragma unroll
    for (int it = 0; it < 8; it++) {
        int idx = tid + it * 256;
        int r = idx >> 4, c4 = idx & 15;
        pa[it] = *(const float4*)&A[(size_t)(rb + r) * N + kb0 + c4 * 4];
    }
    pzh = ((const uint4*)Zh)[(zn * (N / 2) + kb0 / 2 + zw4) >> 2];

    float zc[4][4];
    #pragma unroll
    for (int i = 0; i < 4; i++)
        #pragma unroll
        for (int j = 0; j < 4; j++) zc[i][j] = 0.f;

    for (int cb = 0; cb < 64; cb++) {
        __syncthreads();
        #pragma unroll
        for (int it = 0; it < 8; it++) {
            int idx = tid + it * 256;
            int r = idx >> 4, c4 = idx & 15;
            float4 v = pa[it];
            *(uint2*)&sAh[r * 36 + c4 * 2] =
                make_uint2(packhf(v.x, v.y), packhf(v.z, v.w));
        }
        *(uint4*)&sZh[zn * 36 + zw4] = pzh;
        __syncthreads();

        if (cb < 63) {
            const int ko = kb0 + (cb + 1) * 64;
            #pragma unroll
            for (int it = 0; it < 8; it++) {
                int idx = tid + it * 256;
                int r = idx >> 4, c4 = idx & 15;
                pa[it] = *(const float4*)&A[(size_t)(rb + r) * N + ko + c4 * 4];
            }
            pzh = ((const uint4*)Zh)[(zn * (N / 2) + ko / 2 + zw4) >> 2];
        }

        #pragma unroll
        for (int kt = 0; kt < 4; kt++) {
            const int kw = kt * 8 + t;
            uint32_t ah[4];
            ah[0] = sAh[(w * 16 + qr) * 36 + kw];
            ah[1] = sAh[(w * 16 + qr + 8) * 36 + kw];
            ah[2] = sAh[(w * 16 + qr) * 36 + kw + 4];
            ah[3] = sAh[(w * 16 + qr + 8) * 36 + kw + 4];
            #pragma unroll
            for (int nt = 0; nt < 4; nt++) {
                const int nc = nt * 8 + qr;
                uint32_t bh0 = sZh[nc * 36 + kw], bh1 = sZh[nc * 36 + kw + 4];
                mma_f16(zc[nt], ah, bh0, bh1);
            }
        }
    }

    const int row0 = rb + w * 16 + qr;
    #pragma unroll
    for (int nt = 0; nt < 4; nt++) {
        const int col = nt * 8 + 2 * t;
        Lp[(size_t)row0 * 32 + col]           = zc[nt][0];
        Lp[(size_t)row0 * 32 + col + 1]       = zc[nt][1];
        Lp[(size_t)(row0 + 8) * 32 + col]     = zc[nt][2];
        Lp[(size_t)(row0 + 8) * 32 + col + 1] = zc[nt][3];
    }
}

// Lambda partial sums -> transposed fp16 hi [32][N]
__global__ void lsplit_kernel() {
    int idx = blockIdx.x * blockDim.x + threadIdx.x;
    if (idx >= 2 * 32 * N) return;
    int t = idx >= 32 * N;
    int j = idx - t * 32 * N;
    int n = j / N, k = j - n * N;
    size_t src = (size_t)k * 32 + n;
    float v = (t ? g_LpA1 : g_LpA0)[src] + (t ? g_LpB1 : g_LpB0)[src];
    (t ? g_Lth1 : g_Lth0)[j] = __float2half_rn(v);
}

// -------------------- fused HMMA kernel (ldmatrix fragment loads) -----------
template <int D>
__device__ void ftc(char* smraw, const __half* Xh,
                    const float* Qg, const __half* Lth,
                    const float* Xn, const float* Qn, float* Zg, int qb) {
    constexpr int QS = D + 8;
    __half* sQh  = (__half*)smraw;
    __half* sXhB = sQh + 128 * QS;
    __half* sLhB = sXhB + 2 * 64 * QS;
    float* sXnB = (float*)(sLhB + 2 * 32 * 72);
    float* sRed = (float*)sXhB;            // reused after the chunk loop

    const int tid = threadIdx.x;
    const int g = tid >> 8, wtid = tid & 255;
    const int lane = tid & 31, w = wtid >> 5;
    const int t = lane & 3, qr = lane >> 2;
    const int wq0 = w * 16;
    __half* sXh = sXhB + g * 64 * QS;
    __half* sLh = sLhB + g * 32 * 72;
    float* sXn = sXnB + g * 64;

    // ldmatrix base addresses (loop-invariant; buffers are fixed)
    // A (Q tile, m16k16): lanes 0-7 rows wq0+0..7 @k0, 8-15 rows +8 @k0,
    //                     16-23 rows 0..7 @k0+8, 24-31 rows +8 @k0+8
    const uint32_t aQ = s2u(sQh + (wq0 + (lane & 15)) * QS + ((lane >> 4) << 3));
    // B (X rows, pair of n8k16 tiles): m0 rows 16np+0..7 @k0, m1 same rows @k0+8,
    //                                  m2 rows +8 @k0, m3 rows +8 @k0+8
    const uint32_t aX = s2u(sXh + ((lane & 7) + ((lane >> 4) << 3)) * QS +
                            (((lane >> 3) & 1) << 3));
    const uint32_t aL = s2u(sLh + ((lane & 7) + ((lane >> 4) << 3)) * 72 +
                            (((lane >> 3) & 1) << 3));

    // Q -> SMEM fp16 hi (all 512 threads), then full-CTA sync
    for (int i = tid; i < 128 * D; i += 512) {
        int r = i / D, c = i - r * D;
        sQh[r * QS + c] = __float2half_rn(Qg[(size_t)(qb + r) * D + c]);
    }
    __syncthreads();
    const float qn0 = Qn[qb + wq0 + qr];
    const float qn1 = Qn[qb + wq0 + qr + 8];

    float zc[4][4];
    #pragma unroll
    for (int i = 0; i < 4; i++)
        #pragma unroll
        for (int j = 0; j < 4; j++) zc[i][j] = 0.f;

    for (int it = 0; it < 64; it++) {
        const int xb = (2 * it + g) * 64;
        // ---- stage this group's chunk ----
        #pragma unroll
        for (int i = wtid; i < 64 * (D / 4); i += 256) {
            int r = i / (D / 4), p = i - r * (D / 4);
            uint2 vh = ((const uint2*)Xh)[(size_t)(xb + r) * (D / 4) + p];
            *(uint2*)(sXh + r * QS + p * 4) = vh;
        }
        #pragma unroll
        for (int i = wtid; i < 32 * 16; i += 256) {
            int n = i >> 4, p = i & 15;
            uint2 vh = ((const uint2*)Lth)[(size_t)n * (N / 4) + xb / 4 + p];
            *(uint2*)(sLh + n * 72 + p * 4) = vh;
        }
        if (wtid < 64) sXn[wtid] = Xn[xb + wtid];
        GBAR(g);

        // ---- phase 1: D1[16q x 64x] = Qh . Xh^T (ldmatrix fragments) ----
        float c1[8][4];
        #pragma unroll
        for (int i = 0; i < 8; i++)
            #pragma unroll
            for (int j = 0; j < 4; j++) c1[i][j] = 0.f;

        #pragma unroll
        for (int kt = 0; kt < D / 16; kt++) {
            uint32_t ah[4];
            ldsm4(ah, aQ + kt * 32);
            #pragma unroll
            for (int np = 0; np < 4; np++) {
                uint32_t b[4];
                ldsm4(b, aX + np * (16 * QS * 2) + kt * 32);
                mma_f16(c1[2 * np],     ah, b[0], b[1]);
                mma_f16(c1[2 * np + 1], ah, b[2], b[3]);
            }
        }

        // ---- epilogue: exp -> P hi fragments ----
        uint32_t Ph[4][4];
        #pragma unroll
        for (int kt2 = 0; kt2 < 4; kt2++) {
            #pragma unroll
            for (int s = 0; s < 2; s++) {
                const int nt = 2 * kt2 + s;
                const int x0 = nt * 8 + 2 * t;
                float xna = sXn[x0], xnb = sXn[x0 + 1];
                float p0 = __expf(-0.0078125f * (qn0 + xna - 2.f * c1[nt][0]));
                float p1 = __expf(-0.0078125f * (qn0 + xnb - 2.f * c1[nt][1]));
                float p2 = __expf(-0.0078125f * (qn1 + xna - 2.f * c1[nt][2]));
                float p3 = __expf(-0.0078125f * (qn1 + xnb - 2.f * c1[nt][3]));
                Ph[kt2][2 * s]     = packhf(p0, p1);
                Ph[kt2][2 * s + 1] = packhf(p2, p3);
            }
        }

        // ---- phase 2: z += Ph . Lh^T (ldmatrix fragments) ----
        #pragma unroll
        for (int kt2 = 0; kt2 < 4; kt2++) {
            #pragma unroll
            for (int np = 0; np < 2; np++) {
                uint32_t b[4];
                ldsm4(b, aL + np * (16 * 72 * 2) + kt2 * 32);
                mma_f16(zc[2 * np],     Ph[kt2], b[0], b[1]);
                mma_f16(zc[2 * np + 1], Ph[kt2], b[2], b[3]);
            }
        }
        GBAR(g);
    }

    // ---- combine the two x-half partial sums (full-CTA sync) ----
    __syncthreads();
    const int row0 = wq0 + qr;
    if (g == 1) {
        #pragma unroll
        for (int nt = 0; nt < 4; nt++) {
            const int col = nt * 8 + 2 * t;
            sRed[row0 * 33 + col]           = zc[nt][0];
            sRed[row0 * 33 + col + 1]       = zc[nt][1];
            sRed[(row0 + 8) * 33 + col]     = zc[nt][2];
            sRed[(row0 + 8) * 33 + col + 1] = zc[nt][3];
        }
    }
    __syncthreads();
    if (g == 0) {
        #pragma unroll
        for (int nt = 0; nt < 4; nt++) {
            const int col = nt * 8 + 2 * t;
            float v0 = zc[nt][0] + sRed[row0 * 33 + col];
            float v1 = zc[nt][1] + sRed[row0 * 33 + col + 1];
            float v2 = zc[nt][2] + sRed[(row0 + 8) * 33 + col];
            float v3 = zc[nt][3] + sRed[(row0 + 8) * 33 + col + 1];
            Zg[(size_t)(qb + row0) * 32 + col]           = v0;
            Zg[(size_t)(qb + row0) * 32 + col + 1]       = v1;
            Zg[(size_t)(qb + row0 + 8) * 32 + col]       = v2;
            Zg[(size_t)(qb + row0 + 8) * 32 + col + 1]   = v3;
        }
    }
}

// D=96: (128*104 + 2*64*104 + 2*32*72) half + 2*64 f32 = 62464 + 512
#define FUSED_SMEM 63488

__global__ __launch_bounds__(512, 1) void fusedtc_kernel() {
    extern __shared__ char sm[];
    int task = blockIdx.x >> 6;
    int qb   = (blockIdx.x & 63) * 128;
    if (task == 0)
        ftc<64>(sm, g_Xmh, g_xqm, g_Lth0, g_Xnm, g_qnm, g_zm, qb);
    else
        ftc<96>(sm, g_Xvh, g_xqv, g_Lth1, g_Xnv, g_qnv, g_zv, qb);
}

// -------------------- combine ----------------------------------------------
__global__ void combine_kernel(const float* __restrict__ y_mean,
                               const float* __restrict__ y_var,
                               float* __restrict__ out) {
    int i = blockIdx.x * blockDim.x + threadIdx.x;
    if (i < N * 32)
        out[i] = (y_mean[i] + g_zm[i]) + (y_var[i] + g_zv[i]);
}

// -------------------- launch ------------------------------------------------
extern "C" void kernel_launch(void* const* d_in, const int* in_sizes, int n_in,
                              void* d_out, int out_size) {
    const float* x_mu   = (const float*)d_in[0];
    const float* y_eta  = (const float*)d_in[1];
    const float* y_mean = (const float*)d_in[2];
    const float* y_var  = (const float*)d_in[3];
    const float* X_mean = (const float*)d_in[4];
    const float* X_var  = (const float*)d_in[5];
    const float* Z_mean = (const float*)d_in[6];
    const float* Z_var  = (const float*)d_in[7];
    const float* kMi    = (const float*)d_in[8];
    const float* kVi    = (const float*)d_in[9];
    float* out = (float*)d_out;

    cudaFuncSetAttribute(fusedtc_kernel,
                         cudaFuncAttributeMaxDynamicSharedMemorySize, FUSED_SMEM);

    prep_q_kernel<<<(N * 32 + 255) / 256, 256>>>(x_mu, y_eta, y_mean, y_var);
    prep_X_kernel<<<(N * 32 + 255) / 256, 256>>>(X_mean, X_var);
    zsplit_kernel<<<(2 * 32 * N + 255) / 256, 256>>>(Z_mean, Z_var);
    lambda_hmma_kernel<<<dim3(64, 2, 2), 256>>>(kMi, kVi);
    lsplit_kernel<<<(2 * 32 * N + 255) / 256, 256>>>();
    fusedtc_kernel<<<128, 512, FUSED_SMEM>>>();
    combine_kernel<<<(N * 32 + 255) / 256, 256>>>(y_mean, y_var, out);
}

// round 14
// speedup vs baseline: 1.4464x; 1.1124x over previous
#include <cuda_runtime.h>
#include <cuda_fp16.h>
#include <cstdint>

#define N 8192

// -------------------- device scratch ---------------------------------------
__device__ float g_xqm[N * 64];
__device__ float g_xqv[N * 96];
__device__ float g_qnm[N], g_qnv[N];
__device__ __align__(16) float g_Xnm[N];
__device__ __align__(16) float g_Xnv[N];
__device__ float g_LpA0[N * 32], g_LpB0[N * 32];   // Lambda partials (k-halves)
__device__ float g_LpA1[N * 32], g_LpB1[N * 32];
__device__ float g_zm[N * 32], g_zv[N * 32];
__device__ __align__(16) __half g_Xmh[N * 64];          // X hi (phase1 hi-only)
__device__ __align__(16) __half g_Xvh[N * 96];
__device__ __align__(16) __half g_Lth0[32 * N];         // Lambda^T hi only
__device__ __align__(16) __half g_Lth1[32 * N];
__device__ __align__(16) __half g_Zth0[32 * N];         // Z^T hi only
__device__ __align__(16) __half g_Zth1[32 * N];

// -------------------- mma / ldmatrix / cp.async helpers ---------------------
__device__ __forceinline__ void mma_f16(float c[4], const uint32_t a[4],
                                        uint32_t b0, uint32_t b1) {
    asm volatile(
        "mma.sync.aligned.m16n8k16.row.col.f32.f16.f16.f32 "
        "{%0,%1,%2,%3}, {%4,%5,%6,%7}, {%8,%9}, {%0,%1,%2,%3};"
        : "+f"(c[0]), "+f"(c[1]), "+f"(c[2]), "+f"(c[3])
        : "r"(a[0]), "r"(a[1]), "r"(a[2]), "r"(a[3]), "r"(b0), "r"(b1));
}
__device__ __forceinline__ uint32_t packhf(float lo, float hi) {
    uint32_t r;
    asm("cvt.rn.f16x2.f32 %0, %1, %2;" : "=r"(r) : "f"(hi), "f"(lo));
    return r;
}
__device__ __forceinline__ uint32_t s2u(const void* p) {
    return (uint32_t)__cvta_generic_to_shared(p);
}
__device__ __forceinline__ void ldsm4(uint32_t* r, uint32_t addr) {
    asm volatile("ldmatrix.sync.aligned.m8n8.x4.shared.b16 {%0,%1,%2,%3}, [%4];"
                 : "=r"(r[0]), "=r"(r[1]), "=r"(r[2]), "=r"(r[3]) : "r"(addr));
}
__device__ __forceinline__ void cpasync16(uint32_t dst, const void* src) {
    asm volatile("cp.async.cg.shared.global [%0], [%1], 16;"
                 :: "r"(dst), "l"(src) : "memory");
}
#define CP_COMMIT() asm volatile("cp.async.commit_group;" ::: "memory")
#define CP_WAIT1()  asm volatile("cp.async.wait_group 1;" ::: "memory")
// group-scoped named barrier: 256 threads of group g
#define GBAR(g) asm volatile("bar.sync %0, 256;" :: "r"(1 + (g)) : "memory")

// -------------------- prep kernels ------------------------------------------
__global__ void prep_q_kernel(const float* __restrict__ x_mu,
                              const float* __restrict__ y_eta,
                              const float* __restrict__ y_mean,
                              const float* __restrict__ y_var) {
    int q = (blockIdx.x * blockDim.x + threadIdx.x) >> 5;
    int lane = threadIdx.x & 31;
    if (q >= N) return;
    float a = x_mu[q * 32 + lane];
    float m = y_mean[q * 32 + lane] + y_var[q * 32 + lane];
    float e = 0.01f * y_eta[(N - 1 - q) * 32 + lane];
    g_xqm[q * 64 + lane] = a;       g_xqm[q * 64 + 32 + lane] = m;
    g_xqv[q * 96 + lane] = a;       g_xqv[q * 96 + 32 + lane] = e;
    g_xqv[q * 96 + 64 + lane] = m;
    float nm = a * a + m * m, nv = nm + e * e;
    #pragma unroll
    for (int o = 16; o; o >>= 1) {
        nm += __shfl_xor_sync(0xffffffffu, nm, o);
        nv += __shfl_xor_sync(0xffffffffu, nv, o);
    }
    if (lane == 0) { g_qnm[q] = nm; g_qnv[q] = nv; }
}

__global__ void prep_X_kernel(const float* __restrict__ Xm,
                              const float* __restrict__ Xv) {
    int i = (blockIdx.x * blockDim.x + threadIdx.x) >> 5;
    int lane = threadIdx.x & 31;
    if (i >= N) return;
    float nm = 0.f, nv = 0.f;
    #pragma unroll
    for (int c = 0; c < 64; c += 32) {
        float v = Xm[(size_t)i * 64 + c + lane];
        nm += v * v;
        g_Xmh[(size_t)i * 64 + c + lane] = __float2half_rn(v);
    }
    #pragma unroll
    for (int c = 0; c < 96; c += 32) {
        float v = Xv[(size_t)i * 96 + c + lane];
        nv += v * v;
        g_Xvh[(size_t)i * 96 + c + lane] = __float2half_rn(v);
    }
    #pragma unroll
    for (int o = 16; o; o >>= 1) {
        nm += __shfl_xor_sync(0xffffffffu, nm, o);
        nv += __shfl_xor_sync(0xffffffffu, nv, o);
    }
    if (lane == 0) { g_Xnm[i] = nm; g_Xnv[i] = nv; }
}

// Z -> transposed fp16 hi [32][N]
__global__ void zsplit_kernel(const float* __restrict__ Z0,
                              const float* __restrict__ Z1) {
    int idx = blockIdx.x * blockDim.x + threadIdx.x;
    if (idx >= 2 * 32 * N) return;
    int t = idx >= 32 * N;
    int j = idx - t * 32 * N;
    int n = j / N, k = j - n * N;
    float v = (t ? Z1 : Z0)[(size_t)k * 32 + n];
    (t ? g_Zth1 : g_Zth0)[j] = __float2half_rn(v);
}

// -------------------- Lambda = kXX_inv @ Z on HMMA (hi-only, 1-MMA) ---------
__global__ __launch_bounds__(256, 2) void lambda_hmma_kernel(
    const float* __restrict__ A0, const float* __restrict__ A1) {
    const int task = blockIdx.y, kh = blockIdx.z;
    const float* A = task ? A1 : A0;
    const __half* Zh = task ? g_Zth1 : g_Zth0;
    float* Lp = task ? (kh ? g_LpB1 : g_LpA1) : (kh ? g_LpB0 : g_LpA0);

    __shared__ __align__(16) uint32_t sAh[128 * 36];
    __shared__ __align__(16) uint32_t sZh[32 * 36];

    const int tid = threadIdx.x, lane = tid & 31, w = tid >> 5;
    const int t = lane & 3, qr = lane >> 2;
    const int rb = blockIdx.x * 128;
    const int kb0 = kh * (N / 2);
    const int zn = (tid * 4) >> 5, zw4 = (tid * 4) & 31;

    float4 pa[8];
    uint4 pzh;
    #pragma unroll
    for (int it = 0; it < 8; it++) {
        int idx = tid + it * 256;
        int r = idx >> 4, c4 = idx & 15;
        pa[it] = *(const float4*)&A[(size_t)(rb + r) * N + kb0 + c4 * 4];
    }
    pzh = ((const uint4*)Zh)[(zn * (N / 2) + kb0 / 2 + zw4) >> 2];

    float zc[4][4];
    #pragma unroll
    for (int i = 0; i < 4; i++)
        #pragma unroll
        for (int j = 0; j < 4; j++) zc[i][j] = 0.f;

    for (int cb = 0; cb < 64; cb++) {
        __syncthreads();
        #pragma unroll
        for (int it = 0; it < 8; it++) {
            int idx = tid + it * 256;
            int r = idx >> 4, c4 = idx & 15;
            float4 v = pa[it];
            *(uint2*)&sAh[r * 36 + c4 * 2] =
                make_uint2(packhf(v.x, v.y), packhf(v.z, v.w));
        }
        *(uint4*)&sZh[zn * 36 + zw4] = pzh;
        __syncthreads();

        if (cb < 63) {
            const int ko = kb0 + (cb + 1) * 64;
            #pragma unroll
            for (int it = 0; it < 8; it++) {
                int idx = tid + it * 256;
                int r = idx >> 4, c4 = idx & 15;
                pa[it] = *(const float4*)&A[(size_t)(rb + r) * N + ko + c4 * 4];
            }
            pzh = ((const uint4*)Zh)[(zn * (N / 2) + ko / 2 + zw4) >> 2];
        }

        #pragma unroll
        for (int kt = 0; kt < 4; kt++) {
            const int kw = kt * 8 + t;
            uint32_t ah[4];
            ah[0] = sAh[(w * 16 + qr) * 36 + kw];
            ah[1] = sAh[(w * 16 + qr + 8) * 36 + kw];
            ah[2] = sAh[(w * 16 + qr) * 36 + kw + 4];
            ah[3] = sAh[(w * 16 + qr + 8) * 36 + kw + 4];
            #pragma unroll
            for (int nt = 0; nt < 4; nt++) {
                const int nc = nt * 8 + qr;
                uint32_t bh0 = sZh[nc * 36 + kw], bh1 = sZh[nc * 36 + kw + 4];
                mma_f16(zc[nt], ah, bh0, bh1);
            }
        }
    }

    const int row0 = rb + w * 16 + qr;
    #pragma unroll
    for (int nt = 0; nt < 4; nt++) {
        const int col = nt * 8 + 2 * t;
        Lp[(size_t)row0 * 32 + col]           = zc[nt][0];
        Lp[(size_t)row0 * 32 + col + 1]       = zc[nt][1];
        Lp[(size_t)(row0 + 8) * 32 + col]     = zc[nt][2];
        Lp[(size_t)(row0 + 8) * 32 + col + 1] = zc[nt][3];
    }
}

// Lambda partial sums -> transposed fp16 hi [32][N]
__global__ void lsplit_kernel() {
    int idx = blockIdx.x * blockDim.x + threadIdx.x;
    if (idx >= 2 * 32 * N) return;
    int t = idx >= 32 * N;
    int j = idx - t * 32 * N;
    int n = j / N, k = j - n * N;
    size_t src = (size_t)k * 32 + n;
    float v = (t ? g_LpA1 : g_LpA0)[src] + (t ? g_LpB1 : g_LpB0)[src];
    (t ? g_Lth1 : g_Lth0)[j] = __float2half_rn(v);
}

// -------------------- fused HMMA kernel (cp.async 2-stage + interleave) -----
template <int D>
__device__ void ftc(char* smraw, const __half* Xh,
                    const float* Qg, const __half* Lth,
                    const float* Xn, const float* Qn, float* Zg, int qb) {
    constexpr int QS = D + 8;
    constexpr int XSEG = D / 8;                    // 16B segs per X row
    __half* sQh  = (__half*)smraw;
    __half* sXhB = sQh + 128 * QS;                 // [4][64*QS]  (g*2+b)
    __half* sLhB = sXhB + 4 * 64 * QS;             // [4][32*72]
    float*  sXnB = (float*)(sLhB + 4 * 32 * 72);   // [4][64]
    float*  sRed = (float*)sXhB;                   // reused after chunk loop

    const int tid = threadIdx.x;
    const int g = tid >> 8, wtid = tid & 255;
    const int lane = tid & 31, w = wtid >> 5;
    const int t = lane & 3, qr = lane >> 2;
    const int wq0 = w * 16;
    __half* sXg = sXhB + (2 * g) * 64 * QS;
    __half* sLg = sLhB + (2 * g) * 32 * 72;
    float*  sXng = sXnB + (2 * g) * 64;

    // ldmatrix base addresses (buffer 0; add byte offset per buffer)
    const uint32_t aQ = s2u(sQh + (wq0 + (lane & 15)) * QS + ((lane >> 4) << 3));
    const uint32_t aX = s2u(sXg + ((lane & 7) + ((lane >> 4) << 3)) * QS +
                            (((lane >> 3) & 1) << 3));
    const uint32_t aL = s2u(sLg + ((lane & 7) + ((lane >> 4) << 3)) * 72 +
                            (((lane >> 3) & 1) << 3));

    // stage chunk -> buffer via cp.async (one commit group)
    auto stage = [&](int buf, int chunk) {
        const int xb = chunk * 64;
        __half* dX = sXg + buf * 64 * QS;
        #pragma unroll
        for (int i = wtid; i < 64 * XSEG; i += 256) {
            int r = i / XSEG, s = i - r * XSEG;
            cpasync16(s2u(dX + r * QS + s * 8), Xh + (size_t)(xb + r) * D + s * 8);
        }
        __half* dL = sLg + buf * 32 * 72;
        if (wtid < 256) {
            int n = wtid >> 3, s = wtid & 7;
            cpasync16(s2u(dL + n * 72 + s * 8), Lth + (size_t)n * N + xb + s * 8);
        }
        if (wtid < 16)
            cpasync16(s2u(sXng + buf * 64 + wtid * 4), Xn + xb + wtid * 4);
        CP_COMMIT();
    };

    // Q -> SMEM fp16 hi (all 512 threads)
    for (int i = tid; i < 128 * D; i += 512) {
        int r = i / D, c = i - r * D;
        sQh[r * QS + c] = __float2half_rn(Qg[(size_t)(qb + r) * D + c]);
    }
    // prologue: stage chunks for it=0 and it=1
    stage(0, g);
    stage(1, 2 + g);
    __syncthreads();
    const float qn0 = Qn[qb + wq0 + qr];
    const float qn1 = Qn[qb + wq0 + qr + 8];

    float zc[4][4];
    #pragma unroll
    for (int i = 0; i < 4; i++)
        #pragma unroll
        for (int j = 0; j < 4; j++) zc[i][j] = 0.f;

    for (int it = 0; it < 64; it++) {
        const int buf = it & 1;
        CP_WAIT1();
        GBAR(g);
        const uint32_t aXb = aX + buf * (64 * QS * 2);
        const uint32_t aLb = aL + buf * (32 * 72 * 2);
        const float* xn = sXng + buf * 64;

        // ---- phase 1: D1[16q x 64x] = Qh . Xh^T ----
        float c1[8][4];
        #pragma unroll
        for (int i = 0; i < 8; i++)
            #pragma unroll
            for (int j = 0; j < 4; j++) c1[i][j] = 0.f;

        #pragma unroll
        for (int kt = 0; kt < D / 16; kt++) {
            uint32_t ah[4];
            ldsm4(ah, aQ + kt * 32);
            #pragma unroll
            for (int np = 0; np < 4; np++) {
                uint32_t b[4];
                ldsm4(b, aXb + np * (16 * QS * 2) + kt * 32);
                mma_f16(c1[2 * np],     ah, b[0], b[1]);
                mma_f16(c1[2 * np + 1], ah, b[2], b[3]);
            }
        }

        // ---- epilogue + phase 2 interleaved per kt2 ----
        #pragma unroll
        for (int kt2 = 0; kt2 < 4; kt2++) {
            uint32_t Ph[4];
            #pragma unroll
            for (int s = 0; s < 2; s++) {
                const int nt = 2 * kt2 + s;
                const int x0 = nt * 8 + 2 * t;
                float xna = xn[x0], xnb = xn[x0 + 1];
                float p0 = __expf(-0.0078125f * (qn0 + xna - 2.f * c1[nt][0]));
                float p1 = __expf(-0.0078125f * (qn0 + xnb - 2.f * c1[nt][1]));
                float p2 = __expf(-0.0078125f * (qn1 + xna - 2.f * c1[nt][2]));
                float p3 = __expf(-0.0078125f * (qn1 + xnb - 2.f * c1[nt][3]));
                Ph[2 * s]     = packhf(p0, p1);
                Ph[2 * s + 1] = packhf(p2, p3);
            }
            #pragma unroll
            for (int np = 0; np < 2; np++) {
                uint32_t b[4];
                ldsm4(b, aLb + np * (16 * 72 * 2) + kt2 * 32);
                mma_f16(zc[2 * np],     Ph, b[0], b[1]);
                mma_f16(zc[2 * np + 1], Ph, b[2], b[3]);
            }
        }
        GBAR(g);

        if (it < 62) stage(buf, 2 * (it + 2) + g);
        else CP_COMMIT();                    // empty group keeps wait_group math
    }

    // ---- combine the two x-half partial sums (full-CTA sync) ----
    __syncthreads();
    const int row0 = wq0 + qr;
    if (g == 1) {
        #pragma unroll
        for (int nt = 0; nt < 4; nt++) {
            const int col = nt * 8 + 2 * t;
            sRed[row0 * 33 + col]           = zc[nt][0];
            sRed[row0 * 33 + col + 1]       = zc[nt][1];
            sRed[(row0 + 8) * 33 + col]     = zc[nt][2];
            sRed[(row0 + 8) * 33 + col + 1] = zc[nt][3];
        }
    }
    __syncthreads();
    if (g == 0) {
        #pragma unroll
        for (int nt = 0; nt < 4; nt++) {
            const int col = nt * 8 + 2 * t;
            float v0 = zc[nt][0] + sRed[row0 * 33 + col];
            float v1 = zc[nt][1] + sRed[row0 * 33 + col + 1];
            float v2 = zc[nt][2] + sRed[(row0 + 8) * 33 + col];
            float v3 = zc[nt][3] + sRed[(row0 + 8) * 33 + col + 1];
            Zg[(size_t)(qb + row0) * 32 + col]           = v0;
            Zg[(size_t)(qb + row0) * 32 + col + 1]       = v1;
            Zg[(size_t)(qb + row0 + 8) * 32 + col]       = v2;
            Zg[(size_t)(qb + row0 + 8) * 32 + col + 1]   = v3;
        }
    }
}

// D=96: (128*104 + 4*64*104 + 4*32*72) half + 4*64 f32 + 64 f32 red slack
#define FUSED_SMEM ((128 * 104 + 4 * 64 * 104 + 4 * 32 * 72) * 2 + 4 * 64 * 4 + 256)

__global__ __launch_bounds__(512, 1) void fusedtc_kernel() {
    extern __shared__ char sm[];
    int task = blockIdx.x >> 6;
    int qb   = (blockIdx.x & 63) * 128;
    if (task == 0)
        ftc<64>(sm, g_Xmh, g_xqm, g_Lth0, g_Xnm, g_qnm, g_zm, qb);
    else
        ftc<96>(sm, g_Xvh, g_xqv, g_Lth1, g_Xnv, g_qnv, g_zv, qb);
}

// -------------------- combine ----------------------------------------------
__global__ void combine_kernel(const float* __restrict__ y_mean,
                               const float* __restrict__ y_var,
                               float* __restrict__ out) {
    int i = blockIdx.x * blockDim.x + threadIdx.x;
    if (i < N * 32)
        out[i] = (y_mean[i] + g_zm[i]) + (y_var[i] + g_zv[i]);
}

// -------------------- launch ------------------------------------------------
extern "C" void kernel_launch(void* const* d_in, const int* in_sizes, int n_in,
                              void* d_out, int out_size) {
    const float* x_mu   = (const float*)d_in[0];
    const float* y_eta  = (const float*)d_in[1];
    const float* y_mean = (const float*)d_in[2];
    const float* y_var  = (const float*)d_in[3];
    const float* X_mean = (const float*)d_in[4];
    const float* X_var  = (const float*)d_in[5];
    const float* Z_mean = (const float*)d_in[6];
    const float* Z_var  = (const float*)d_in[7];
    const float* kMi    = (const float*)d_in[8];
    const float* kVi    = (const float*)d_in[9];
    float* out = (float*)d_out;

    cudaFuncSetAttribute(fusedtc_kernel,
                         cudaFuncAttributeMaxDynamicSharedMemorySize, FUSED_SMEM);

    prep_q_kernel<<<(N * 32 + 255) / 256, 256>>>(x_mu, y_eta, y_mean, y_var);
    prep_X_kernel<<<(N * 32 + 255) / 256, 256>>>(X_mean, X_var);
    zsplit_kernel<<<(2 * 32 * N + 255) / 256, 256>>>(Z_mean, Z_var);
    lambda_hmma_kernel<<<dim3(64, 2, 2), 256>>>(kMi, kVi);
    lsplit_kernel<<<(2 * 32 * N + 255) / 256, 256>>>();
    fusedtc_kernel<<<128, 512, FUSED_SMEM>>>();
    combine_kernel<<<(N * 32 + 255) / 256, 256>>>(y_mean, y_var, out);
}